// round 1
// baseline (speedup 1.0000x reference)
#include <cuda_runtime.h>
#include <cuda_bf16.h>
#include <math.h>

// ---------------- problem constants ----------------
#define B_      4
#define L_      8192
#define DMODEL  256
#define DINNER  512
#define DSTATE  64
#define NH      4
#define HD      128
#define CHUNKSZ 128
#define NC      64          // L_/CHUNKSZ
#define CONVD   640
#define DPROJ   1156
#define HIMG    256
#define WIMG    512
#define HO      64
#define WO      128

// ---------------- static scratch (device globals; no runtime allocation) ----
__device__ float g_feats[(size_t)2*B_*L_*DMODEL];     // 16.8M  downsampled features
__device__ float g_zx   [(size_t)2*B_*L_*DPROJ];      // 75.8M  in_proj output
__device__ float g_xbc  [(size_t)2*B_*L_*CONVD];      // 41.9M  post-conv xBC (s=0 conv+silu, s=1 raw)
__device__ float g_dt   [(size_t)2*B_*L_*NH];
__device__ float g_cum  [(size_t)2*B_*L_*NH];
__device__ float g_y    [(size_t)2*B_*L_*DINNER];     // 33.6M
__device__ float g_state[(size_t)2*B_*NC*NH*HD*DSTATE]; // 16.8M per-chunk states
__device__ float g_hprev[(size_t)2*B_*NC*NH*HD*DSTATE]; // 16.8M carried states

// ============================================================================
// 1. Downsample conv: 3->256, 4x4 stride 4.  Block handles 16 ow positions.
//    dyn smem: weights 256*48 + patches 16*48 floats
// ============================================================================
__global__ void downsample_kernel(const float* __restrict__ left,
                                  const float* __restrict__ right,
                                  const float* __restrict__ dw,
                                  const float* __restrict__ db) {
    extern __shared__ float sm[];
    float* sw = sm;            // [256][48]
    float* sp = sm + DMODEL*48; // [16][48]
    int bi = blockIdx.x;
    int wt = bi % (WO/16);
    int oh = (bi / (WO/16)) % HO;
    int b  = (bi / (WO/16 * HO)) % B_;
    int s  = bi / (WO/16 * HO * B_);
    const float* img = s ? right : left;
    int tid = threadIdx.x;
    for (int i = tid; i < DMODEL*48; i += 256) sw[i] = dw[i];
    int ow0 = wt * 16;
    for (int i = tid; i < 16*48; i += 256) {
        int pos = i / 48, j = i % 48;
        int ci = j / 16, kh = (j % 16) / 4, kw = j % 4;
        sp[i] = img[((size_t)(b*3 + ci)*HIMG + (oh*4 + kh))*WIMG + (ow0 + pos)*4 + kw];
    }
    __syncthreads();
    int c = tid;   // 256 threads == 256 channels
    float bias = db[c];
    for (int pos = 0; pos < 16; pos++) {
        float acc = bias;
        #pragma unroll
        for (int j = 0; j < 48; j++) acc += sp[pos*48 + j] * sw[c*48 + j];
        int l = oh*WO + ow0 + pos;
        g_feats[((size_t)(s*B_ + b)*L_ + l)*DMODEL + c] = acc;
    }
}

// ============================================================================
// 2. SGEMM (NT): C[m,n] = sum_k A[m,k]*Bw[n,k].  BM=BN=128, BK=16, 256 thr, 8x8.
//    M must be a multiple of 128 (true for all our launches); N guarded.
// ============================================================================
__global__ void sgemm_nt(const float* __restrict__ A, const float* __restrict__ Bw,
                         float* __restrict__ C, int M, int N, int K) {
    __shared__ float As[16][128];
    __shared__ float Bs[16][128];
    int tid = threadIdx.x;
    int tx = tid % 16, ty = tid / 16;
    int m0 = blockIdx.y * 128, n0 = blockIdx.x * 128;
    float acc[8][8];
    #pragma unroll
    for (int i = 0; i < 8; i++)
        #pragma unroll
        for (int j = 0; j < 8; j++) acc[i][j] = 0.f;

    for (int k0 = 0; k0 < K; k0 += 16) {
        for (int i = tid; i < 128*16; i += 256) {
            int r = i >> 4, k = i & 15;
            As[k][r] = A[(size_t)(m0 + r)*K + k0 + k];
            int n = n0 + r;
            Bs[k][r] = (n < N) ? Bw[(size_t)n*K + k0 + k] : 0.f;
        }
        __syncthreads();
        #pragma unroll
        for (int kk = 0; kk < 16; kk++) {
            float4 a0 = *(const float4*)&As[kk][ty*8];
            float4 a1 = *(const float4*)&As[kk][ty*8 + 4];
            float4 b0 = *(const float4*)&Bs[kk][tx*8];
            float4 b1 = *(const float4*)&Bs[kk][tx*8 + 4];
            float ar[8] = {a0.x,a0.y,a0.z,a0.w,a1.x,a1.y,a1.z,a1.w};
            float br[8] = {b0.x,b0.y,b0.z,b0.w,b1.x,b1.y,b1.z,b1.w};
            #pragma unroll
            for (int i = 0; i < 8; i++)
                #pragma unroll
                for (int j = 0; j < 8; j++) acc[i][j] += ar[i]*br[j];
        }
        __syncthreads();
    }
    #pragma unroll
    for (int i = 0; i < 8; i++) {
        int gm = m0 + ty*8 + i;
        #pragma unroll
        for (int j = 0; j < 8; j++) {
            int gn = n0 + tx*8 + j;
            if (gn < N) C[(size_t)gm*N + gn] = acc[i][j];
        }
    }
}

// ============================================================================
// 3. conv1d (causal, depthwise, s=0 only: conv+bias+silu; s=1: raw copy)
// ============================================================================
__global__ void conv_split_kernel(const float* __restrict__ cw,
                                  const float* __restrict__ cb) {
    size_t idx = (size_t)blockIdx.x * 256 + threadIdx.x;
    if (idx >= (size_t)2*B_*L_*CONVD) return;
    int ch = (int)(idx % CONVD);
    size_t t = idx / CONVD;
    int l  = (int)(t % L_);
    int sb = (int)(t / L_);          // [0, 2*B): s = sb>>2
    float out;
    if (sb < B_) {  // s == 0: conv + silu
        float acc = cb[ch];
        #pragma unroll
        for (int k = 0; k < 4; k++) {
            int ls = l + k - 3;
            if (ls >= 0)
                acc += cw[ch*4 + k] * g_zx[((size_t)sb*L_ + ls)*DPROJ + 512 + ch];
        }
        out = acc / (1.f + expf(-acc));
    } else {        // s == 1: raw
        out = g_zx[((size_t)sb*L_ + l)*DPROJ + 512 + ch];
    }
    g_xbc[((size_t)sb*L_ + l)*CONVD + ch] = out;
}

// ============================================================================
// 4. dt = softplus(zx[...,1152+h] + dt_bias[h])
// ============================================================================
__global__ void dt_kernel(const float* __restrict__ dt_bias) {
    size_t idx = (size_t)blockIdx.x * 256 + threadIdx.x;
    if (idx >= (size_t)2*B_*L_*NH) return;
    int h = (int)(idx % NH);
    size_t row = idx / NH;
    float v = g_zx[row*DPROJ + (DINNER + CONVD) + h] + dt_bias[h];
    g_dt[idx] = (v > 20.f) ? v : log1pf(expf(v));
}

// ============================================================================
// 5. per-chunk cumsum of dt * A  (A = -exp(A_log))
// ============================================================================
__global__ void cum_kernel(const float* __restrict__ A_log) {
    int t = blockIdx.x * blockDim.x + threadIdx.x;
    if (t >= 2*B_*NC*NH) return;
    int h = t % NH;
    int c = (t / NH) % NC;
    int sb = t / (NH * NC);
    float An = -expf(A_log[h]);
    float acc = 0.f;
    for (int i = 0; i < CHUNKSZ; i++) {
        size_t off = ((size_t)sb*L_ + c*CHUNKSZ + i)*NH + h;
        acc += g_dt[off] * An;
        g_cum[off] = acc;
    }
}

// ============================================================================
// 6. Intra-chunk SSD: y (intra + D*x) and per-chunk state S.
//    One block per (s,b,chunk,head). 256 threads, ~199KB dyn smem.
//    Scan s uses: dt/cum/C from stream s; x/B from stream 1-s.
// ============================================================================
__global__ void chunk_kernel(const float* __restrict__ Dv) {
    extern __shared__ float sm[];
    float* Bsm = sm;                 // [128][65] padded
    float* Csm = Bsm + 128*65;       // [128][65]
    float* Xs  = Csm + 128*65;       // [128][128] j-major
    float* Gs  = Xs + 128*128;       // [128][128]
    float* cum = Gs + 128*128;       // [128]
    float* dts = cum + 128;          // [128]
    float* wj  = dts + 128;          // [128]

    int bi = blockIdx.x, tid = threadIdx.x;
    int h  = bi % NH;
    int c  = (bi / NH) % NC;
    int b  = (bi / (NH*NC)) % B_;
    int s  = bi / (NH*NC*B_);
    int sb  = s*B_ + b;
    int sbo = (1 - s)*B_ + b;
    size_t l0 = (size_t)c * CHUNKSZ;

    for (int i = tid; i < 128*64; i += 256) {
        int j = i >> 6, n = i & 63;
        Bsm[j*65 + n] = g_xbc[((size_t)sbo*L_ + l0 + j)*CONVD + 512 + n];
        Csm[j*65 + n] = g_xbc[((size_t)sb *L_ + l0 + j)*CONVD + 576 + n];
    }
    for (int i = tid; i < 128*128; i += 256) {
        int j = i >> 7, p = i & 127;
        Xs[i] = g_xbc[((size_t)sbo*L_ + l0 + j)*CONVD + h*HD + p];
    }
    if (tid < 128) {
        size_t off = ((size_t)sb*L_ + l0 + tid)*NH + h;
        cum[tid] = g_cum[off];
        dts[tid] = g_dt[off];
    }
    __syncthreads();
    if (tid < 128) wj[tid] = dts[tid] * expf(cum[127] - cum[tid]);

    // G[i][j] = (C_i . B_j) * exp(cum_i - cum_j) * dt_j  for j<=i else 0
    for (int idx = tid; idx < 128*128; idx += 256) {
        int i = idx >> 7, j = idx & 127;
        float g = 0.f;
        if (j <= i) {
            float cb = 0.f;
            #pragma unroll
            for (int n = 0; n < 64; n++) cb += Csm[i*65 + n] * Bsm[j*65 + n];
            g = cb * expf(cum[i] - cum[j]) * dts[j];
        }
        Gs[idx] = g;
    }
    __syncthreads();

    // y[i][p] = sum_j G[i][j]*x[j][p] + D[h]*x[i][p]
    {
        int pp = tid & 31, ig = tid >> 5;
        float acc[16][4];
        #pragma unroll
        for (int r = 0; r < 16; r++)
            #pragma unroll
            for (int q = 0; q < 4; q++) acc[r][q] = 0.f;
        for (int j = 0; j < 128; j++) {
            float xv0 = Xs[j*128 + pp];
            float xv1 = Xs[j*128 + pp + 32];
            float xv2 = Xs[j*128 + pp + 64];
            float xv3 = Xs[j*128 + pp + 96];
            #pragma unroll
            for (int r = 0; r < 16; r++) {
                float g = Gs[(ig + 8*r)*128 + j];
                acc[r][0] += g*xv0; acc[r][1] += g*xv1;
                acc[r][2] += g*xv2; acc[r][3] += g*xv3;
            }
        }
        float Dh = Dv[h];
        #pragma unroll
        for (int r = 0; r < 16; r++) {
            int i = ig + 8*r;
            #pragma unroll
            for (int q = 0; q < 4; q++) {
                int p = pp + 32*q;
                float val = acc[r][q] + Dh * Xs[i*128 + p];
                g_y[((size_t)sb*L_ + l0 + i)*DINNER + h*HD + p] = val;
            }
        }
    }

    // S[p][n] = sum_j B_j[n] * wj[j] * x[j][p]
    {
        int n  = tid & 63;
        int p0 = tid >> 6;     // 0..3
        float sacc[32];
        #pragma unroll
        for (int t2 = 0; t2 < 32; t2++) sacc[t2] = 0.f;
        for (int j = 0; j < 128; j++) {
            float bw = Bsm[j*65 + n] * wj[j];
            const float* xr = &Xs[j*128 + p0];
            #pragma unroll
            for (int t2 = 0; t2 < 32; t2++) sacc[t2] += bw * xr[4*t2];
        }
        size_t sbase = (size_t)bi * (HD*DSTATE);
        #pragma unroll
        for (int t2 = 0; t2 < 32; t2++)
            g_state[sbase + (size_t)(p0 + 4*t2)*64 + n] = sacc[t2];
    }
}

// ============================================================================
// 7. Sequential inter-chunk scan: h_{c+1} = h_c * dec_c + S_c; store h_c (pre).
//    One block per (s,b,head): 32 blocks, 256 thr, 32 elems each.
// ============================================================================
__global__ void scan_kernel() {
    int t = blockIdx.x;      // 2*B*NH
    int h = t % NH;
    int sb = t / NH;
    int tid = threadIdx.x;
    float hreg[32];
    #pragma unroll
    for (int t2 = 0; t2 < 32; t2++) hreg[t2] = 0.f;
    for (int c = 0; c < NC; c++) {
        float dec = expf(g_cum[((size_t)sb*L_ + c*CHUNKSZ + 127)*NH + h]);
        size_t base = (((size_t)sb*NC + c)*NH + h) * (HD*DSTATE);
        #pragma unroll
        for (int t2 = 0; t2 < 32; t2++) {
            size_t o = base + tid + 256*t2;
            g_hprev[o] = hreg[t2];
            hreg[t2] = hreg[t2]*dec + g_state[o];
        }
    }
}

// ============================================================================
// 8. Inter-chunk contribution: y[i][p] += exp(cum_i) * sum_n C_i[n]*hprev[p][n]
// ============================================================================
__global__ void interchunk_kernel() {
    extern __shared__ float sm[];
    float* Hs  = sm;             // [128][65]
    float* Csm = Hs + 128*65;    // [128][65]
    float* cum = Csm + 128*65;   // [128]

    int bi = blockIdx.x, tid = threadIdx.x;
    int h  = bi % NH;
    int c  = (bi / NH) % NC;
    int b  = (bi / (NH*NC)) % B_;
    int s  = bi / (NH*NC*B_);
    int sb = s*B_ + b;
    size_t l0 = (size_t)c * CHUNKSZ;

    size_t hbase = (size_t)bi * (HD*DSTATE);
    for (int i = tid; i < 128*64; i += 256) {
        int p = i >> 6, n = i & 63;
        Hs[p*65 + n]  = g_hprev[hbase + i];
        Csm[p*65 + n] = g_xbc[((size_t)sb*L_ + l0 + p)*CONVD + 576 + n];
    }
    if (tid < 128) cum[tid] = g_cum[((size_t)sb*L_ + l0 + tid)*NH + h];
    __syncthreads();

    int pp = tid & 31, ii = tid >> 5;
    float acc[16][4];
    #pragma unroll
    for (int r = 0; r < 16; r++)
        #pragma unroll
        for (int q = 0; q < 4; q++) acc[r][q] = 0.f;
    for (int n = 0; n < 64; n++) {
        float hv0 = Hs[(pp)*65 + n];
        float hv1 = Hs[(pp + 32)*65 + n];
        float hv2 = Hs[(pp + 64)*65 + n];
        float hv3 = Hs[(pp + 96)*65 + n];
        #pragma unroll
        for (int r = 0; r < 16; r++) {
            float cv = Csm[(ii + 8*r)*65 + n];
            acc[r][0] += cv*hv0; acc[r][1] += cv*hv1;
            acc[r][2] += cv*hv2; acc[r][3] += cv*hv3;
        }
    }
    #pragma unroll
    for (int r = 0; r < 16; r++) {
        int i = ii + 8*r;
        float ci = expf(cum[i]);
        #pragma unroll
        for (int q = 0; q < 4; q++) {
            int p = pp + 32*q;
            size_t off = ((size_t)sb*L_ + l0 + i)*DINNER + h*HD + p;
            g_y[off] += ci * acc[r][q];
        }
    }
}

// ============================================================================
// 9. Gated RMSNorm (in place on g_y): y = y*silu(z); y *= rsqrt(mean(y^2)+eps)*w
// ============================================================================
__global__ void rmsnorm_kernel(const float* __restrict__ norm_w) {
    int row = blockIdx.x;        // 2*B*L rows
    int tid = threadIdx.x;       // 128
    __shared__ float red[4];
    size_t ybase = (size_t)row * DINNER;
    size_t zbase = (size_t)row * DPROJ;
    float g[4];
    float ss = 0.f;
    #pragma unroll
    for (int t = 0; t < 4; t++) {
        int d = tid + 128*t;
        float z = g_zx[zbase + d];
        float yv = g_y[ybase + d];
        float gg = yv * (z / (1.f + expf(-z)));
        g[t] = gg;
        ss += gg*gg;
    }
    #pragma unroll
    for (int o = 16; o > 0; o >>= 1) ss += __shfl_xor_sync(0xFFFFFFFFu, ss, o);
    if ((tid & 31) == 0) red[tid >> 5] = ss;
    __syncthreads();
    float tot = red[0] + red[1] + red[2] + red[3];
    float scale = rsqrtf(tot / (float)DINNER + 1e-5f);
    #pragma unroll
    for (int t = 0; t < 4; t++) {
        int d = tid + 128*t;
        g_y[ybase + d] = g[t] * scale * norm_w[d];
    }
}

// ============================================================================
extern "C" void kernel_launch(void* const* d_in, const int* in_sizes, int n_in,
                              void* d_out, int out_size) {
    const float* left   = (const float*)d_in[0];
    const float* right  = (const float*)d_in[1];
    const float* dw     = (const float*)d_in[2];
    const float* db     = (const float*)d_in[3];
    const float* inpw   = (const float*)d_in[4];
    const float* cw     = (const float*)d_in[5];
    const float* cb     = (const float*)d_in[6];
    const float* dtb    = (const float*)d_in[7];
    const float* alog   = (const float*)d_in[8];
    const float* Dv     = (const float*)d_in[9];
    const float* nw     = (const float*)d_in[10];
    const float* outw   = (const float*)d_in[11];
    float* out          = (float*)d_out;

    float *p_feats, *p_zx, *p_y;
    cudaGetSymbolAddress((void**)&p_feats, g_feats);
    cudaGetSymbolAddress((void**)&p_zx,    g_zx);
    cudaGetSymbolAddress((void**)&p_y,     g_y);

    const int ds_smem    = (DMODEL*48 + 16*48) * 4;          // 52224
    const int chunk_smem = (2*128*65 + 2*128*128 + 3*128) * 4; // 199168
    const int ic_smem    = (2*128*65 + 128) * 4;             // 67072
    cudaFuncSetAttribute(downsample_kernel, cudaFuncAttributeMaxDynamicSharedMemorySize, ds_smem);
    cudaFuncSetAttribute(chunk_kernel,      cudaFuncAttributeMaxDynamicSharedMemorySize, chunk_smem);
    cudaFuncSetAttribute(interchunk_kernel, cudaFuncAttributeMaxDynamicSharedMemorySize, ic_smem);

    // 1. downsample
    downsample_kernel<<<2*B_*HO*(WO/16), 256, ds_smem>>>(left, right, dw, db);

    // 2. in_proj GEMM: (2*B*L, 256) @ (1156, 256)^T
    {
        dim3 grid((DPROJ + 127)/128, (2*B_*L_)/128);
        sgemm_nt<<<grid, 256>>>(p_feats, inpw, p_zx, 2*B_*L_, DPROJ, DMODEL);
    }

    // 3. conv1d + split
    {
        size_t tot = (size_t)2*B_*L_*CONVD;
        conv_split_kernel<<<(unsigned)((tot + 255)/256), 256>>>(cw, cb);
    }

    // 4. dt softplus
    {
        size_t tot = (size_t)2*B_*L_*NH;
        dt_kernel<<<(unsigned)((tot + 255)/256), 256>>>(dtb);
    }

    // 5. per-chunk cumsum
    cum_kernel<<<(2*B_*NC*NH + 255)/256, 256>>>(alog);

    // 6. intra-chunk SSD
    chunk_kernel<<<2*B_*NC*NH, 256, chunk_smem>>>(Dv);

    // 7. inter-chunk sequential scan
    scan_kernel<<<2*B_*NH, 256>>>();

    // 8. inter-chunk contribution
    interchunk_kernel<<<2*B_*NC*NH, 256, ic_smem>>>();

    // 9. gated rmsnorm (in place)
    rmsnorm_kernel<<<2*B_*L_, 128>>>(nw);

    // 10. out_proj GEMM: (2*B*L, 512) @ (256, 512)^T -> d_out
    {
        dim3 grid((DMODEL + 127)/128, (2*B_*L_)/128);
        sgemm_nt<<<grid, 256>>>(p_y, outw, out, 2*B_*L_, DMODEL, DINNER);
    }
}

// round 2
// speedup vs baseline: 1.3546x; 1.3546x over previous
#include <cuda_runtime.h>
#include <cuda_bf16.h>
#include <math.h>

// ---------------- problem constants ----------------
#define B_      4
#define L_      8192
#define DMODEL  256
#define DINNER  512
#define DSTATE  64
#define NH      4
#define HD      128
#define CHUNKSZ 128
#define NC      64          // L_/CHUNKSZ
#define CONVD   640
#define DPROJ   1156
#define HIMG    256
#define WIMG    512
#define HO      64
#define WO      128

// ---------------- static scratch (device globals; no runtime allocation) ----
__device__ float g_feats[(size_t)2*B_*L_*DMODEL];
__device__ float g_zx   [(size_t)2*B_*L_*DPROJ];
__device__ float g_xbc  [(size_t)2*B_*L_*CONVD];
__device__ float g_dt   [(size_t)2*B_*L_*NH];
__device__ float g_cum  [(size_t)2*B_*L_*NH];
__device__ float g_y    [(size_t)2*B_*L_*DINNER];
__device__ float g_state[(size_t)2*B_*NC*NH*HD*DSTATE];
__device__ float g_hprev[(size_t)2*B_*NC*NH*HD*DSTATE];

// ============================================================================
// 1. Downsample conv: 3->256, 4x4 stride 4.
// ============================================================================
__global__ void downsample_kernel(const float* __restrict__ left,
                                  const float* __restrict__ right,
                                  const float* __restrict__ dw,
                                  const float* __restrict__ db) {
    extern __shared__ float sm[];
    float* sw = sm;             // [256][48]
    float* sp = sm + DMODEL*48; // [16][48]
    int bi = blockIdx.x;
    int wt = bi % (WO/16);
    int oh = (bi / (WO/16)) % HO;
    int b  = (bi / (WO/16 * HO)) % B_;
    int s  = bi / (WO/16 * HO * B_);
    const float* img = s ? right : left;
    int tid = threadIdx.x;
    for (int i = tid; i < DMODEL*48; i += 256) sw[i] = dw[i];
    int ow0 = wt * 16;
    for (int i = tid; i < 16*48; i += 256) {
        int pos = i / 48, j = i % 48;
        int ci = j / 16, kh = (j % 16) / 4, kw = j % 4;
        sp[i] = img[((size_t)(b*3 + ci)*HIMG + (oh*4 + kh))*WIMG + (ow0 + pos)*4 + kw];
    }
    __syncthreads();
    int c = tid;
    float bias = db[c];
    for (int pos = 0; pos < 16; pos++) {
        float acc = bias;
        #pragma unroll
        for (int j = 0; j < 48; j++) acc += sp[pos*48 + j] * sw[c*48 + j];
        int l = oh*WO + ow0 + pos;
        g_feats[((size_t)(s*B_ + b)*L_ + l)*DMODEL + c] = acc;
    }
}

// ============================================================================
// 2. SGEMM (NT) v2: C[m,n] = sum_k A[m,k]*Bw[n,k].
//    BM=BN=128, BK=8, 256 threads, 8x8 micro-tile, double-buffered smem,
//    conflict-free smem fill (row stride 132) and reads, float4 everywhere.
//    Requires: M % 128 == 0, K % 8 == 0, N % 4 == 0 (all true here).
// ============================================================================
__global__ void __launch_bounds__(256)
sgemm_nt_v2(const float* __restrict__ A, const float* __restrict__ Bw,
            float* __restrict__ C, int M, int N, int K) {
    __shared__ float As[2][8*132];
    __shared__ float Bs[2][8*132];
    int tid = threadIdx.x;
    int tx = tid & 15, ty = tid >> 4;
    int m0 = blockIdx.y * 128, n0 = blockIdx.x * 128;
    int lm = tid >> 1;            // 0..127
    int lk = (tid & 1) * 4;       // 0 or 4

    const float* Aptr = A + (size_t)(m0 + lm) * K + lk;
    int brow = n0 + lm;
    const float* Bptr = Bw + (size_t)brow * K + lk;
    bool bvalid = brow < N;

    float acc[8][8];
    #pragma unroll
    for (int i = 0; i < 8; i++)
        #pragma unroll
        for (int j = 0; j < 8; j++) acc[i][j] = 0.f;

    // prologue: tile 0
    float4 na = *(const float4*)Aptr;
    float4 nb = bvalid ? *(const float4*)Bptr : make_float4(0.f,0.f,0.f,0.f);
    {
        float av[4] = {na.x, na.y, na.z, na.w};
        float bv[4] = {nb.x, nb.y, nb.z, nb.w};
        #pragma unroll
        for (int u = 0; u < 4; u++) {
            As[0][(lk+u)*132 + lm] = av[u];
            Bs[0][(lk+u)*132 + lm] = bv[u];
        }
    }
    __syncthreads();

    int buf = 0;
    for (int k0 = 8; k0 <= K; k0 += 8) {
        if (k0 < K) {
            na = *(const float4*)(Aptr + k0);
            nb = bvalid ? *(const float4*)(Bptr + k0) : make_float4(0.f,0.f,0.f,0.f);
        }
        #pragma unroll
        for (int kk = 0; kk < 8; kk++) {
            float4 a0 = *(const float4*)&As[buf][kk*132 + ty*4];
            float4 a1 = *(const float4*)&As[buf][kk*132 + 64 + ty*4];
            float4 b0 = *(const float4*)&Bs[buf][kk*132 + tx*4];
            float4 b1 = *(const float4*)&Bs[buf][kk*132 + 64 + tx*4];
            float ar[8] = {a0.x,a0.y,a0.z,a0.w,a1.x,a1.y,a1.z,a1.w};
            float br[8] = {b0.x,b0.y,b0.z,b0.w,b1.x,b1.y,b1.z,b1.w};
            #pragma unroll
            for (int i = 0; i < 8; i++)
                #pragma unroll
                for (int j = 0; j < 8; j++) acc[i][j] += ar[i]*br[j];
        }
        if (k0 < K) {
            buf ^= 1;
            float av[4] = {na.x, na.y, na.z, na.w};
            float bv[4] = {nb.x, nb.y, nb.z, nb.w};
            #pragma unroll
            for (int u = 0; u < 4; u++) {
                As[buf][(lk+u)*132 + lm] = av[u];
                Bs[buf][(lk+u)*132 + lm] = bv[u];
            }
            __syncthreads();
        }
    }

    // epilogue: rows {ty*4+i, 64+ty*4+i}, cols {n0+tx*4, n0+64+tx*4}
    #pragma unroll
    for (int g = 0; g < 2; g++) {
        #pragma unroll
        for (int i = 0; i < 4; i++) {
            int gm = m0 + g*64 + ty*4 + i;
            int ri = g*4 + i;
            int n1 = n0 + tx*4;
            int n2 = n0 + 64 + tx*4;
            if (n1 < N) {
                float4 v = make_float4(acc[ri][0], acc[ri][1], acc[ri][2], acc[ri][3]);
                *(float4*)&C[(size_t)gm*N + n1] = v;
            }
            if (n2 < N) {
                float4 v = make_float4(acc[ri][4], acc[ri][5], acc[ri][6], acc[ri][7]);
                *(float4*)&C[(size_t)gm*N + n2] = v;
            }
        }
    }
}

// ============================================================================
// 3. conv1d (causal, depthwise, s=0: conv+bias+silu; s=1: raw copy). float4.
// ============================================================================
__global__ void conv_split_kernel(const float* __restrict__ cw,
                                  const float* __restrict__ cb) {
    size_t idx = (size_t)blockIdx.x * 256 + threadIdx.x;   // float4 index
    size_t total4 = (size_t)2*B_*L_*CONVD/4;
    if (idx >= total4) return;
    int c4 = (int)(idx % (CONVD/4));
    size_t t = idx / (CONVD/4);
    int l  = (int)(t % L_);
    int sb = (int)(t / L_);
    int ch = c4 * 4;
    float4 out;
    if (sb < B_) {  // conv + silu
        float acc[4] = {cb[ch], cb[ch+1], cb[ch+2], cb[ch+3]};
        #pragma unroll
        for (int k = 0; k < 4; k++) {
            int ls = l + k - 3;
            if (ls >= 0) {
                float4 v = *(const float4*)&g_zx[((size_t)sb*L_ + ls)*DPROJ + 512 + ch];
                acc[0] += cw[(ch+0)*4 + k] * v.x;
                acc[1] += cw[(ch+1)*4 + k] * v.y;
                acc[2] += cw[(ch+2)*4 + k] * v.z;
                acc[3] += cw[(ch+3)*4 + k] * v.w;
            }
        }
        out.x = acc[0] / (1.f + __expf(-acc[0]));
        out.y = acc[1] / (1.f + __expf(-acc[1]));
        out.z = acc[2] / (1.f + __expf(-acc[2]));
        out.w = acc[3] / (1.f + __expf(-acc[3]));
    } else {
        out = *(const float4*)&g_zx[((size_t)sb*L_ + l)*DPROJ + 512 + ch];
    }
    *(float4*)&g_xbc[((size_t)sb*L_ + l)*CONVD + ch] = out;
}

// ============================================================================
// 4. dt = softplus(zx[...,1152+h] + dt_bias[h])
// ============================================================================
__global__ void dt_kernel(const float* __restrict__ dt_bias) {
    size_t idx = (size_t)blockIdx.x * 256 + threadIdx.x;
    if (idx >= (size_t)2*B_*L_*NH) return;
    int h = (int)(idx % NH);
    size_t row = idx / NH;
    float v = g_zx[row*DPROJ + (DINNER + CONVD) + h] + dt_bias[h];
    g_dt[idx] = (v > 20.f) ? v : log1pf(__expf(v));
}

// ============================================================================
// 5. per-chunk cumsum of dt * A
// ============================================================================
__global__ void cum_kernel(const float* __restrict__ A_log) {
    int t = blockIdx.x * blockDim.x + threadIdx.x;
    if (t >= 2*B_*NC*NH) return;
    int h = t % NH;
    int c = (t / NH) % NC;
    int sb = t / (NH * NC);
    float An = -__expf(A_log[h]);
    float acc = 0.f;
    for (int i = 0; i < CHUNKSZ; i++) {
        size_t off = ((size_t)sb*L_ + c*CHUNKSZ + i)*NH + h;
        acc += g_dt[off] * An;
        g_cum[off] = acc;
    }
}

// ============================================================================
// 6. Intra-chunk SSD
// ============================================================================
__global__ void chunk_kernel(const float* __restrict__ Dv) {
    extern __shared__ float sm[];
    float* Bsm = sm;                 // [128][65]
    float* Csm = Bsm + 128*65;       // [128][65]
    float* Xs  = Csm + 128*65;       // [128][128]
    float* Gs  = Xs + 128*128;       // [128][128]
    float* cum = Gs + 128*128;       // [128]
    float* dts = cum + 128;          // [128]
    float* wj  = dts + 128;          // [128]

    int bi = blockIdx.x, tid = threadIdx.x;
    int h  = bi % NH;
    int c  = (bi / NH) % NC;
    int b  = (bi / (NH*NC)) % B_;
    int s  = bi / (NH*NC*B_);
    int sb  = s*B_ + b;
    int sbo = (1 - s)*B_ + b;
    size_t l0 = (size_t)c * CHUNKSZ;

    for (int i = tid; i < 128*64; i += 256) {
        int j = i >> 6, n = i & 63;
        Bsm[j*65 + n] = g_xbc[((size_t)sbo*L_ + l0 + j)*CONVD + 512 + n];
        Csm[j*65 + n] = g_xbc[((size_t)sb *L_ + l0 + j)*CONVD + 576 + n];
    }
    for (int i = tid; i < 128*128; i += 256) {
        int j = i >> 7, p = i & 127;
        Xs[i] = g_xbc[((size_t)sbo*L_ + l0 + j)*CONVD + h*HD + p];
    }
    if (tid < 128) {
        size_t off = ((size_t)sb*L_ + l0 + tid)*NH + h;
        cum[tid] = g_cum[off];
        dts[tid] = g_dt[off];
    }
    __syncthreads();
    if (tid < 128) wj[tid] = dts[tid] * __expf(cum[127] - cum[tid]);

    for (int idx = tid; idx < 128*128; idx += 256) {
        int i = idx >> 7, j = idx & 127;
        float g = 0.f;
        if (j <= i) {
            float cb = 0.f;
            #pragma unroll
            for (int n = 0; n < 64; n++) cb += Csm[i*65 + n] * Bsm[j*65 + n];
            g = cb * __expf(cum[i] - cum[j]) * dts[j];
        }
        Gs[idx] = g;
    }
    __syncthreads();

    {
        int pp = tid & 31, ig = tid >> 5;
        float acc[16][4];
        #pragma unroll
        for (int r = 0; r < 16; r++)
            #pragma unroll
            for (int q = 0; q < 4; q++) acc[r][q] = 0.f;
        for (int j = 0; j < 128; j++) {
            float xv0 = Xs[j*128 + pp];
            float xv1 = Xs[j*128 + pp + 32];
            float xv2 = Xs[j*128 + pp + 64];
            float xv3 = Xs[j*128 + pp + 96];
            #pragma unroll
            for (int r = 0; r < 16; r++) {
                float g = Gs[(ig + 8*r)*128 + j];
                acc[r][0] += g*xv0; acc[r][1] += g*xv1;
                acc[r][2] += g*xv2; acc[r][3] += g*xv3;
            }
        }
        float Dh = Dv[h];
        #pragma unroll
        for (int r = 0; r < 16; r++) {
            int i = ig + 8*r;
            #pragma unroll
            for (int q = 0; q < 4; q++) {
                int p = pp + 32*q;
                float val = acc[r][q] + Dh * Xs[i*128 + p];
                g_y[((size_t)sb*L_ + l0 + i)*DINNER + h*HD + p] = val;
            }
        }
    }

    {
        int n  = tid & 63;
        int p0 = tid >> 6;
        float sacc[32];
        #pragma unroll
        for (int t2 = 0; t2 < 32; t2++) sacc[t2] = 0.f;
        for (int j = 0; j < 128; j++) {
            float bw = Bsm[j*65 + n] * wj[j];
            const float* xr = &Xs[j*128 + p0];
            #pragma unroll
            for (int t2 = 0; t2 < 32; t2++) sacc[t2] += bw * xr[4*t2];
        }
        size_t sbase = (size_t)bi * (HD*DSTATE);
        #pragma unroll
        for (int t2 = 0; t2 < 32; t2++)
            g_state[sbase + (size_t)(p0 + 4*t2)*64 + n] = sacc[t2];
    }
}

// ============================================================================
// 7. Sequential inter-chunk scan
// ============================================================================
__global__ void scan_kernel() {
    int t = blockIdx.x;
    int h = t % NH;
    int sb = t / NH;
    int tid = threadIdx.x;
    float hreg[32];
    #pragma unroll
    for (int t2 = 0; t2 < 32; t2++) hreg[t2] = 0.f;
    for (int c = 0; c < NC; c++) {
        float dec = __expf(g_cum[((size_t)sb*L_ + c*CHUNKSZ + 127)*NH + h]);
        size_t base = (((size_t)sb*NC + c)*NH + h) * (HD*DSTATE);
        #pragma unroll
        for (int t2 = 0; t2 < 32; t2++) {
            size_t o = base + tid + 256*t2;
            g_hprev[o] = hreg[t2];
            hreg[t2] = hreg[t2]*dec + g_state[o];
        }
    }
}

// ============================================================================
// 8. Inter-chunk contribution
// ============================================================================
__global__ void interchunk_kernel() {
    extern __shared__ float sm[];
    float* Hs  = sm;             // [128][65]
    float* Csm = Hs + 128*65;    // [128][65]
    float* cum = Csm + 128*65;   // [128]

    int bi = blockIdx.x, tid = threadIdx.x;
    int h  = bi % NH;
    int c  = (bi / NH) % NC;
    int b  = (bi / (NH*NC)) % B_;
    int s  = bi / (NH*NC*B_);
    int sb = s*B_ + b;
    size_t l0 = (size_t)c * CHUNKSZ;

    size_t hbase = (size_t)bi * (HD*DSTATE);
    for (int i = tid; i < 128*64; i += 256) {
        int p = i >> 6, n = i & 63;
        Hs[p*65 + n]  = g_hprev[hbase + i];
        Csm[p*65 + n] = g_xbc[((size_t)sb*L_ + l0 + p)*CONVD + 576 + n];
    }
    if (tid < 128) cum[tid] = g_cum[((size_t)sb*L_ + l0 + tid)*NH + h];
    __syncthreads();

    int pp = tid & 31, ii = tid >> 5;
    float acc[16][4];
    #pragma unroll
    for (int r = 0; r < 16; r++)
        #pragma unroll
        for (int q = 0; q < 4; q++) acc[r][q] = 0.f;
    for (int n = 0; n < 64; n++) {
        float hv0 = Hs[(pp)*65 + n];
        float hv1 = Hs[(pp + 32)*65 + n];
        float hv2 = Hs[(pp + 64)*65 + n];
        float hv3 = Hs[(pp + 96)*65 + n];
        #pragma unroll
        for (int r = 0; r < 16; r++) {
            float cv = Csm[(ii + 8*r)*65 + n];
            acc[r][0] += cv*hv0; acc[r][1] += cv*hv1;
            acc[r][2] += cv*hv2; acc[r][3] += cv*hv3;
        }
    }
    #pragma unroll
    for (int r = 0; r < 16; r++) {
        int i = ii + 8*r;
        float ci = __expf(cum[i]);
        #pragma unroll
        for (int q = 0; q < 4; q++) {
            int p = pp + 32*q;
            size_t off = ((size_t)sb*L_ + l0 + i)*DINNER + h*HD + p;
            g_y[off] += ci * acc[r][q];
        }
    }
}

// ============================================================================
// 9. Gated RMSNorm (in place)
// ============================================================================
__global__ void rmsnorm_kernel(const float* __restrict__ norm_w) {
    int row = blockIdx.x;
    int tid = threadIdx.x;
    __shared__ float red[4];
    size_t ybase = (size_t)row * DINNER;
    size_t zbase = (size_t)row * DPROJ;
    float g[4];
    float ss = 0.f;
    #pragma unroll
    for (int t = 0; t < 4; t++) {
        int d = tid + 128*t;
        float z = g_zx[zbase + d];
        float yv = g_y[ybase + d];
        float gg = yv * (z / (1.f + __expf(-z)));
        g[t] = gg;
        ss += gg*gg;
    }
    #pragma unroll
    for (int o = 16; o > 0; o >>= 1) ss += __shfl_xor_sync(0xFFFFFFFFu, ss, o);
    if ((tid & 31) == 0) red[tid >> 5] = ss;
    __syncthreads();
    float tot = red[0] + red[1] + red[2] + red[3];
    float scale = rsqrtf(tot / (float)DINNER + 1e-5f);
    #pragma unroll
    for (int t = 0; t < 4; t++) {
        int d = tid + 128*t;
        g_y[ybase + d] = g[t] * scale * norm_w[d];
    }
}

// ============================================================================
extern "C" void kernel_launch(void* const* d_in, const int* in_sizes, int n_in,
                              void* d_out, int out_size) {
    const float* left   = (const float*)d_in[0];
    const float* right  = (const float*)d_in[1];
    const float* dw     = (const float*)d_in[2];
    const float* db     = (const float*)d_in[3];
    const float* inpw   = (const float*)d_in[4];
    const float* cw     = (const float*)d_in[5];
    const float* cb     = (const float*)d_in[6];
    const float* dtb    = (const float*)d_in[7];
    const float* alog   = (const float*)d_in[8];
    const float* Dv     = (const float*)d_in[9];
    const float* nw     = (const float*)d_in[10];
    const float* outw   = (const float*)d_in[11];
    float* out          = (float*)d_out;

    float *p_feats, *p_zx, *p_y;
    cudaGetSymbolAddress((void**)&p_feats, g_feats);
    cudaGetSymbolAddress((void**)&p_zx,    g_zx);
    cudaGetSymbolAddress((void**)&p_y,     g_y);

    const int ds_smem    = (DMODEL*48 + 16*48) * 4;
    const int chunk_smem = (2*128*65 + 2*128*128 + 3*128) * 4;
    const int ic_smem    = (2*128*65 + 128) * 4;
    cudaFuncSetAttribute(downsample_kernel, cudaFuncAttributeMaxDynamicSharedMemorySize, ds_smem);
    cudaFuncSetAttribute(chunk_kernel,      cudaFuncAttributeMaxDynamicSharedMemorySize, chunk_smem);
    cudaFuncSetAttribute(interchunk_kernel, cudaFuncAttributeMaxDynamicSharedMemorySize, ic_smem);

    downsample_kernel<<<2*B_*HO*(WO/16), 256, ds_smem>>>(left, right, dw, db);

    {   // in_proj: (65536, 256) @ (1156, 256)^T
        dim3 grid((DPROJ + 127)/128, (2*B_*L_)/128);
        sgemm_nt_v2<<<grid, 256>>>(p_feats, inpw, p_zx, 2*B_*L_, DPROJ, DMODEL);
    }

    {
        size_t tot4 = (size_t)2*B_*L_*CONVD/4;
        conv_split_kernel<<<(unsigned)((tot4 + 255)/256), 256>>>(cw, cb);
    }

    {
        size_t tot = (size_t)2*B_*L_*NH;
        dt_kernel<<<(unsigned)((tot + 255)/256), 256>>>(dtb);
    }

    cum_kernel<<<(2*B_*NC*NH + 255)/256, 256>>>(alog);

    chunk_kernel<<<2*B_*NC*NH, 256, chunk_smem>>>(Dv);

    scan_kernel<<<2*B_*NH, 256>>>();

    interchunk_kernel<<<2*B_*NC*NH, 256, ic_smem>>>();

    rmsnorm_kernel<<<2*B_*L_, 128>>>(nw);

    {   // out_proj: (65536, 512) @ (256, 512)^T
        dim3 grid((DMODEL + 127)/128, (2*B_*L_)/128);
        sgemm_nt_v2<<<grid, 256>>>(p_y, outw, out, 2*B_*L_, DMODEL, DINNER);
    }
}

// round 4
// speedup vs baseline: 1.7303x; 1.2774x over previous
#include <cuda_runtime.h>
#include <cuda_bf16.h>
#include <math.h>
#include <stdint.h>

// ---------------- problem constants ----------------
#define B_      4
#define L_      8192
#define DMODEL  256
#define DINNER  512
#define DSTATE  64
#define NH      4
#define HD      128
#define CHUNKSZ 128
#define NC      64
#define CONVD   640
#define DPROJ   1156
#define DPROJ_PAD 1280
#define HIMG    256
#define WIMG    512
#define HO      64
#define WO      128

// ---------------- static scratch ----------------
__device__ float g_feats[(size_t)2*B_*L_*DMODEL];
__device__ float g_zx   [(size_t)2*B_*L_*DPROJ];
__device__ float g_xbc  [(size_t)2*B_*L_*CONVD];
__device__ float g_dt   [(size_t)2*B_*L_*NH];
__device__ float g_cum  [(size_t)2*B_*L_*NH];
__device__ float g_y    [(size_t)2*B_*L_*DINNER];
__device__ float g_state[(size_t)2*B_*NC*NH*HD*DSTATE];
__device__ float g_hprev[(size_t)2*B_*NC*NH*HD*DSTATE];
// split-bf16 operands
__device__ __nv_bfloat16 g_ah[(size_t)2*B_*L_*DINNER];
__device__ __nv_bfloat16 g_al[(size_t)2*B_*L_*DINNER];
__device__ __nv_bfloat16 g_bh[(size_t)DPROJ_PAD*DMODEL];
__device__ __nv_bfloat16 g_bl[(size_t)DPROJ_PAD*DMODEL];

// ---------------- mma.sync helpers (baseline PTX, ok at compute_103) --------
__device__ __forceinline__ uint32_t smem_to_u32(const void* p) {
    uint32_t a;
    asm("{ .reg .u64 t; cvta.to.shared.u64 t, %1; cvt.u32.u64 %0, t; }" : "=r"(a) : "l"(p));
    return a;
}
__device__ __forceinline__ uint32_t swz(uint32_t o) { return o ^ ((o >> 3) & 0x70); }

__device__ __forceinline__ void cp_async16(uint32_t saddr, const void* gptr) {
    asm volatile("cp.async.cg.shared.global [%0], [%1], 16;" :: "r"(saddr), "l"(gptr));
}
#define CP_COMMIT() asm volatile("cp.async.commit_group;" ::: "memory")
#define CP_WAIT(n)  asm volatile("cp.async.wait_group %0;" :: "n"(n) : "memory")

__device__ __forceinline__ void ldsm_x4(uint32_t* r, uint32_t addr) {
    asm volatile("ldmatrix.sync.aligned.m8n8.x4.shared.b16 {%0,%1,%2,%3}, [%4];"
        : "=r"(r[0]), "=r"(r[1]), "=r"(r[2]), "=r"(r[3]) : "r"(addr));
}
__device__ __forceinline__ void ldsm_x2(uint32_t* r, uint32_t addr) {
    asm volatile("ldmatrix.sync.aligned.m8n8.x2.shared.b16 {%0,%1}, [%2];"
        : "=r"(r[0]), "=r"(r[1]) : "r"(addr));
}
__device__ __forceinline__ void mma_bf16(float* c, const uint32_t* a, const uint32_t* b) {
    asm volatile("mma.sync.aligned.m16n8k16.row.col.f32.bf16.bf16.f32 "
        "{%0,%1,%2,%3}, {%4,%5,%6,%7}, {%8,%9}, {%0,%1,%2,%3};"
        : "+f"(c[0]), "+f"(c[1]), "+f"(c[2]), "+f"(c[3])
        : "r"(a[0]), "r"(a[1]), "r"(a[2]), "r"(a[3]), "r"(b[0]), "r"(b[1]));
}

// ============================================================================
// split-bf16 tensor GEMM: C[M,N] = A[M,K]*B[N,K]^T in ~fp32 precision.
// BM=BN=128, BK=64, 256 threads (8 warps, 4x2), warp tile 32x64.
// cp.async double-buffered smem; 3 mma passes (AhBh + AhBl + AlBh).
// Requires M%128==0, K%64==0, Npad%128==0, N even.
// ============================================================================
__global__ void __launch_bounds__(256)
mma_gemm(const __nv_bfloat16* __restrict__ Ah, const __nv_bfloat16* __restrict__ Al,
         const __nv_bfloat16* __restrict__ Bh, const __nv_bfloat16* __restrict__ Bl,
         float* __restrict__ C, int M, int N, int K) {
    extern __shared__ char smem[];
    uint32_t sbase = smem_to_u32(smem);
    int tid = threadIdx.x, wid = tid >> 5, lane = tid & 31;
    int m0 = blockIdx.y * 128, n0 = blockIdx.x * 128;
    int wm = wid & 3, wn = wid >> 2;

    float acc[2][8][4];
    #pragma unroll
    for (int mt = 0; mt < 2; mt++)
        #pragma unroll
        for (int nt = 0; nt < 8; nt++)
            #pragma unroll
            for (int q = 0; q < 4; q++) acc[mt][nt][q] = 0.f;

    const int KT = K >> 6;
    int lrow = tid >> 3, lc8 = tid & 7;

    // stage s base = s*65536; tiles: Ah +0, Al +16384, Bh +32768, Bl +49152
    // issue stage for k-chunk kt into buffer (kt&1)
    auto issue = [&](int kt) {
        uint32_t so = (uint32_t)(kt & 1) << 16;
        #pragma unroll
        for (int u = 0; u < 4; u++) {
            int row = lrow + 32 * u;
            uint32_t sw = swz((uint32_t)row * 128 + lc8 * 16);
            size_t aoff = ((size_t)(m0 + row) * K + kt * 64 + lc8 * 8);
            size_t boff = ((size_t)(n0 + row) * K + kt * 64 + lc8 * 8);
            cp_async16(sbase + so + sw,         Ah + aoff);
            cp_async16(sbase + so + 16384 + sw, Al + aoff);
            cp_async16(sbase + so + 32768 + sw, Bh + boff);
            cp_async16(sbase + so + 49152 + sw, Bl + boff);
        }
        CP_COMMIT();
    };

    issue(0);

    for (int kt = 0; kt < KT; kt++) {
        bool has_next = (kt + 1 < KT);
        if (has_next) { issue(kt + 1); CP_WAIT(1); }
        else          { CP_WAIT(0); }
        __syncthreads();

        uint32_t so = (uint32_t)(kt & 1) << 16;
        #pragma unroll
        for (int ks = 0; ks < 4; ks++) {
            // A fragments (hi & lo) for 2 m16 tiles
            uint32_t ah[2][4], alr[2][4];
            #pragma unroll
            for (int mt = 0; mt < 2; mt++) {
                int row = wm * 32 + mt * 16 + (lane & 15);
                int kb  = ks * 32 + ((lane >> 4) << 4);
                uint32_t off = swz((uint32_t)row * 128 + kb);
                ldsm_x4(ah[mt],  sbase + so + off);
                ldsm_x4(alr[mt], sbase + so + 16384 + off);
            }
            int l2 = lane & 15;
            int nrow = wn * 64 + (l2 & 7);
            int kb2  = ks * 32 + ((l2 >> 3) << 4);
            #pragma unroll
            for (int nt = 0; nt < 8; nt++) {
                uint32_t bh[2], bl[2];
                uint32_t off = swz((uint32_t)(nrow + nt * 8) * 128 + kb2);
                ldsm_x2(bh, sbase + so + 32768 + off);
                ldsm_x2(bl, sbase + so + 49152 + off);
                #pragma unroll
                for (int mt = 0; mt < 2; mt++) {
                    mma_bf16(acc[mt][nt], ah[mt],  bh);
                    mma_bf16(acc[mt][nt], ah[mt],  bl);
                    mma_bf16(acc[mt][nt], alr[mt], bh);
                }
            }
        }
        __syncthreads();
    }

    // epilogue
    int r_base = m0 + wm * 32 + (lane >> 2);
    int c_base = n0 + wn * 64 + 2 * (lane & 3);
    #pragma unroll
    for (int mt = 0; mt < 2; mt++) {
        #pragma unroll
        for (int nt = 0; nt < 8; nt++) {
            int c = c_base + nt * 8;
            if (c < N) {
                int r = r_base + mt * 16;
                *(float2*)&C[(size_t)r * N + c]       = make_float2(acc[mt][nt][0], acc[mt][nt][1]);
                *(float2*)&C[(size_t)(r + 8) * N + c] = make_float2(acc[mt][nt][2], acc[mt][nt][3]);
            }
        }
    }
}

// ============================================================================
// split-bf16 conversion: hi = bf16(v), lo = bf16(v - hi)
// ============================================================================
__global__ void cvt_split4(const float* __restrict__ src,
                           __nv_bfloat16* __restrict__ hi,
                           __nv_bfloat16* __restrict__ lo, size_t n4) {
    size_t i = (size_t)blockIdx.x * 256 + threadIdx.x;
    if (i >= n4) return;
    float4 v = *(const float4*)(src + i * 4);
    __nv_bfloat16 h0 = __float2bfloat16_rn(v.x), h1 = __float2bfloat16_rn(v.y);
    __nv_bfloat16 h2 = __float2bfloat16_rn(v.z), h3 = __float2bfloat16_rn(v.w);
    __nv_bfloat162 H0 = __nv_bfloat162(h0, h1), H1 = __nv_bfloat162(h2, h3);
    __nv_bfloat162 L0 = __nv_bfloat162(__float2bfloat16_rn(v.x - __bfloat162float(h0)),
                                       __float2bfloat16_rn(v.y - __bfloat162float(h1)));
    __nv_bfloat162 L1 = __nv_bfloat162(__float2bfloat16_rn(v.z - __bfloat162float(h2)),
                                       __float2bfloat16_rn(v.w - __bfloat162float(h3)));
    *(__nv_bfloat162*)(hi + i * 4)     = H0;
    *(__nv_bfloat162*)(hi + i * 4 + 2) = H1;
    *(__nv_bfloat162*)(lo + i * 4)     = L0;
    *(__nv_bfloat162*)(lo + i * 4 + 2) = L1;
}

__global__ void cvt_split_pad(const float* __restrict__ src,
                              __nv_bfloat16* __restrict__ hi,
                              __nv_bfloat16* __restrict__ lo,
                              int N, int K, int Npad) {
    size_t i = (size_t)blockIdx.x * 256 + threadIdx.x;
    if (i >= (size_t)Npad * K) return;
    int n = (int)(i / K);
    float v = (n < N) ? src[i] : 0.f;
    __nv_bfloat16 h = __float2bfloat16_rn(v);
    hi[i] = h;
    lo[i] = __float2bfloat16_rn(v - __bfloat162float(h));
}

// ============================================================================
// 1. Downsample conv
// ============================================================================
__global__ void downsample_kernel(const float* __restrict__ left,
                                  const float* __restrict__ right,
                                  const float* __restrict__ dw,
                                  const float* __restrict__ db) {
    extern __shared__ float sm[];
    float* sw = sm;
    float* sp = sm + DMODEL*48;
    int bi = blockIdx.x;
    int wt = bi % (WO/16);
    int oh = (bi / (WO/16)) % HO;
    int b  = (bi / (WO/16 * HO)) % B_;
    int s  = bi / (WO/16 * HO * B_);
    const float* img = s ? right : left;
    int tid = threadIdx.x;
    for (int i = tid; i < DMODEL*48; i += 256) sw[i] = dw[i];
    int ow0 = wt * 16;
    for (int i = tid; i < 16*48; i += 256) {
        int pos = i / 48, j = i % 48;
        int ci = j / 16, kh = (j % 16) / 4, kw = j % 4;
        sp[i] = img[((size_t)(b*3 + ci)*HIMG + (oh*4 + kh))*WIMG + (ow0 + pos)*4 + kw];
    }
    __syncthreads();
    int c = tid;
    float bias = db[c];
    for (int pos = 0; pos < 16; pos++) {
        float acc = bias;
        #pragma unroll
        for (int j = 0; j < 48; j++) acc += sp[pos*48 + j] * sw[c*48 + j];
        int l = oh*WO + ow0 + pos;
        g_feats[((size_t)(s*B_ + b)*L_ + l)*DMODEL + c] = acc;
    }
}

// ============================================================================
// 3. conv1d + split (float4)
// ============================================================================
__global__ void conv_split_kernel(const float* __restrict__ cw,
                                  const float* __restrict__ cb) {
    size_t idx = (size_t)blockIdx.x * 256 + threadIdx.x;
    size_t total4 = (size_t)2*B_*L_*CONVD/4;
    if (idx >= total4) return;
    int c4 = (int)(idx % (CONVD/4));
    size_t t = idx / (CONVD/4);
    int l  = (int)(t % L_);
    int sb = (int)(t / L_);
    int ch = c4 * 4;
    float4 out;
    if (sb < B_) {
        float acc[4] = {cb[ch], cb[ch+1], cb[ch+2], cb[ch+3]};
        #pragma unroll
        for (int k = 0; k < 4; k++) {
            int ls = l + k - 3;
            if (ls >= 0) {
                float4 v = *(const float4*)&g_zx[((size_t)sb*L_ + ls)*DPROJ + 512 + ch];
                acc[0] += cw[(ch+0)*4 + k] * v.x;
                acc[1] += cw[(ch+1)*4 + k] * v.y;
                acc[2] += cw[(ch+2)*4 + k] * v.z;
                acc[3] += cw[(ch+3)*4 + k] * v.w;
            }
        }
        out.x = acc[0] / (1.f + __expf(-acc[0]));
        out.y = acc[1] / (1.f + __expf(-acc[1]));
        out.z = acc[2] / (1.f + __expf(-acc[2]));
        out.w = acc[3] / (1.f + __expf(-acc[3]));
    } else {
        out = *(const float4*)&g_zx[((size_t)sb*L_ + l)*DPROJ + 512 + ch];
    }
    *(float4*)&g_xbc[((size_t)sb*L_ + l)*CONVD + ch] = out;
}

// ============================================================================
// 4. dt softplus
// ============================================================================
__global__ void dt_kernel(const float* __restrict__ dt_bias) {
    size_t idx = (size_t)blockIdx.x * 256 + threadIdx.x;
    if (idx >= (size_t)2*B_*L_*NH) return;
    int h = (int)(idx % NH);
    size_t row = idx / NH;
    float v = g_zx[row*DPROJ + (DINNER + CONVD) + h] + dt_bias[h];
    g_dt[idx] = (v > 20.f) ? v : log1pf(__expf(v));
}

// ============================================================================
// 5. per-chunk cumsum
// ============================================================================
__global__ void cum_kernel(const float* __restrict__ A_log) {
    int t = blockIdx.x * blockDim.x + threadIdx.x;
    if (t >= 2*B_*NC*NH) return;
    int h = t % NH;
    int c = (t / NH) % NC;
    int sb = t / (NH * NC);
    float An = -__expf(A_log[h]);
    float acc = 0.f;
    for (int i = 0; i < CHUNKSZ; i++) {
        size_t off = ((size_t)sb*L_ + c*CHUNKSZ + i)*NH + h;
        acc += g_dt[off] * An;
        g_cum[off] = acc;
    }
}

// ============================================================================
// 6. Intra-chunk SSD
// ============================================================================
__global__ void chunk_kernel(const float* __restrict__ Dv) {
    extern __shared__ float sm[];
    float* Bsm = sm;
    float* Csm = Bsm + 128*65;
    float* Xs  = Csm + 128*65;
    float* Gs  = Xs + 128*128;
    float* cum = Gs + 128*128;
    float* dts = cum + 128;
    float* wj  = dts + 128;

    int bi = blockIdx.x, tid = threadIdx.x;
    int h  = bi % NH;
    int c  = (bi / NH) % NC;
    int b  = (bi / (NH*NC)) % B_;
    int s  = bi / (NH*NC*B_);
    int sb  = s*B_ + b;
    int sbo = (1 - s)*B_ + b;
    size_t l0 = (size_t)c * CHUNKSZ;

    for (int i = tid; i < 128*64; i += 256) {
        int j = i >> 6, n = i & 63;
        Bsm[j*65 + n] = g_xbc[((size_t)sbo*L_ + l0 + j)*CONVD + 512 + n];
        Csm[j*65 + n] = g_xbc[((size_t)sb *L_ + l0 + j)*CONVD + 576 + n];
    }
    for (int i = tid; i < 128*128; i += 256) {
        int j = i >> 7, p = i & 127;
        Xs[i] = g_xbc[((size_t)sbo*L_ + l0 + j)*CONVD + h*HD + p];
    }
    if (tid < 128) {
        size_t off = ((size_t)sb*L_ + l0 + tid)*NH + h;
        cum[tid] = g_cum[off];
        dts[tid] = g_dt[off];
    }
    __syncthreads();
    if (tid < 128) wj[tid] = dts[tid] * __expf(cum[127] - cum[tid]);

    for (int idx = tid; idx < 128*128; idx += 256) {
        int i = idx >> 7, j = idx & 127;
        float g = 0.f;
        if (j <= i) {
            float cb = 0.f;
            #pragma unroll
            for (int n = 0; n < 64; n++) cb += Csm[i*65 + n] * Bsm[j*65 + n];
            g = cb * __expf(cum[i] - cum[j]) * dts[j];
        }
        Gs[idx] = g;
    }
    __syncthreads();

    {
        int pp = tid & 31, ig = tid >> 5;
        float acc[16][4];
        #pragma unroll
        for (int r = 0; r < 16; r++)
            #pragma unroll
            for (int q = 0; q < 4; q++) acc[r][q] = 0.f;
        for (int j = 0; j < 128; j++) {
            float xv0 = Xs[j*128 + pp];
            float xv1 = Xs[j*128 + pp + 32];
            float xv2 = Xs[j*128 + pp + 64];
            float xv3 = Xs[j*128 + pp + 96];
            #pragma unroll
            for (int r = 0; r < 16; r++) {
                float g = Gs[(ig + 8*r)*128 + j];
                acc[r][0] += g*xv0; acc[r][1] += g*xv1;
                acc[r][2] += g*xv2; acc[r][3] += g*xv3;
            }
        }
        float Dh = Dv[h];
        #pragma unroll
        for (int r = 0; r < 16; r++) {
            int i = ig + 8*r;
            #pragma unroll
            for (int q = 0; q < 4; q++) {
                int p = pp + 32*q;
                float val = acc[r][q] + Dh * Xs[i*128 + p];
                g_y[((size_t)sb*L_ + l0 + i)*DINNER + h*HD + p] = val;
            }
        }
    }

    {
        int n  = tid & 63;
        int p0 = tid >> 6;
        float sacc[32];
        #pragma unroll
        for (int t2 = 0; t2 < 32; t2++) sacc[t2] = 0.f;
        for (int j = 0; j < 128; j++) {
            float bw = Bsm[j*65 + n] * wj[j];
            const float* xr = &Xs[j*128 + p0];
            #pragma unroll
            for (int t2 = 0; t2 < 32; t2++) sacc[t2] += bw * xr[4*t2];
        }
        size_t sbase = (size_t)bi * (HD*DSTATE);
        #pragma unroll
        for (int t2 = 0; t2 < 32; t2++)
            g_state[sbase + (size_t)(p0 + 4*t2)*64 + n] = sacc[t2];
    }
}

// ============================================================================
// 7. Sequential inter-chunk scan
// ============================================================================
__global__ void scan_kernel() {
    int t = blockIdx.x;
    int h = t % NH;
    int sb = t / NH;
    int tid = threadIdx.x;
    float hreg[32];
    #pragma unroll
    for (int t2 = 0; t2 < 32; t2++) hreg[t2] = 0.f;
    for (int c = 0; c < NC; c++) {
        float dec = __expf(g_cum[((size_t)sb*L_ + c*CHUNKSZ + 127)*NH + h]);
        size_t base = (((size_t)sb*NC + c)*NH + h) * (HD*DSTATE);
        #pragma unroll
        for (int t2 = 0; t2 < 32; t2++) {
            size_t o = base + tid + 256*t2;
            g_hprev[o] = hreg[t2];
            hreg[t2] = hreg[t2]*dec + g_state[o];
        }
    }
}

// ============================================================================
// 8. Inter-chunk contribution
// ============================================================================
__global__ void interchunk_kernel() {
    extern __shared__ float sm[];
    float* Hs  = sm;
    float* Csm = Hs + 128*65;
    float* cum = Csm + 128*65;

    int bi = blockIdx.x, tid = threadIdx.x;
    int h  = bi % NH;
    int c  = (bi / NH) % NC;
    int b  = (bi / (NH*NC)) % B_;
    int s  = bi / (NH*NC*B_);
    int sb = s*B_ + b;
    size_t l0 = (size_t)c * CHUNKSZ;

    size_t hbase = (size_t)bi * (HD*DSTATE);
    for (int i = tid; i < 128*64; i += 256) {
        int p = i >> 6, n = i & 63;
        Hs[p*65 + n]  = g_hprev[hbase + i];
        Csm[p*65 + n] = g_xbc[((size_t)sb*L_ + l0 + p)*CONVD + 576 + n];
    }
    if (tid < 128) cum[tid] = g_cum[((size_t)sb*L_ + l0 + tid)*NH + h];
    __syncthreads();

    int pp = tid & 31, ii = tid >> 5;
    float acc[16][4];
    #pragma unroll
    for (int r = 0; r < 16; r++)
        #pragma unroll
        for (int q = 0; q < 4; q++) acc[r][q] = 0.f;
    for (int n = 0; n < 64; n++) {
        float hv0 = Hs[(pp)*65 + n];
        float hv1 = Hs[(pp + 32)*65 + n];
        float hv2 = Hs[(pp + 64)*65 + n];
        float hv3 = Hs[(pp + 96)*65 + n];
        #pragma unroll
        for (int r = 0; r < 16; r++) {
            float cv = Csm[(ii + 8*r)*65 + n];
            acc[r][0] += cv*hv0; acc[r][1] += cv*hv1;
            acc[r][2] += cv*hv2; acc[r][3] += cv*hv3;
        }
    }
    #pragma unroll
    for (int r = 0; r < 16; r++) {
        int i = ii + 8*r;
        float ci = __expf(cum[i]);
        #pragma unroll
        for (int q = 0; q < 4; q++) {
            int p = pp + 32*q;
            size_t off = ((size_t)sb*L_ + l0 + i)*DINNER + h*HD + p;
            g_y[off] += ci * acc[r][q];
        }
    }
}

// ============================================================================
// 9. Gated RMSNorm (in place)
// ============================================================================
__global__ void rmsnorm_kernel(const float* __restrict__ norm_w) {
    int row = blockIdx.x;
    int tid = threadIdx.x;
    __shared__ float red[4];
    size_t ybase = (size_t)row * DINNER;
    size_t zbase = (size_t)row * DPROJ;
    float g[4];
    float ss = 0.f;
    #pragma unroll
    for (int t = 0; t < 4; t++) {
        int d = tid + 128*t;
        float z = g_zx[zbase + d];
        float yv = g_y[ybase + d];
        float gg = yv * (z / (1.f + __expf(-z)));
        g[t] = gg;
        ss += gg*gg;
    }
    #pragma unroll
    for (int o = 16; o > 0; o >>= 1) ss += __shfl_xor_sync(0xFFFFFFFFu, ss, o);
    if ((tid & 31) == 0) red[tid >> 5] = ss;
    __syncthreads();
    float tot = red[0] + red[1] + red[2] + red[3];
    float scale = rsqrtf(tot / (float)DINNER + 1e-5f);
    #pragma unroll
    for (int t = 0; t < 4; t++) {
        int d = tid + 128*t;
        g_y[ybase + d] = g[t] * scale * norm_w[d];
    }
}

// ============================================================================
extern "C" void kernel_launch(void* const* d_in, const int* in_sizes, int n_in,
                              void* d_out, int out_size) {
    const float* left   = (const float*)d_in[0];
    const float* right  = (const float*)d_in[1];
    const float* dw     = (const float*)d_in[2];
    const float* db     = (const float*)d_in[3];
    const float* inpw   = (const float*)d_in[4];
    const float* cw     = (const float*)d_in[5];
    const float* cb     = (const float*)d_in[6];
    const float* dtb    = (const float*)d_in[7];
    const float* alog   = (const float*)d_in[8];
    const float* Dv     = (const float*)d_in[9];
    const float* nw     = (const float*)d_in[10];
    const float* outw   = (const float*)d_in[11];
    float* out          = (float*)d_out;

    float *p_feats, *p_zx, *p_y;
    __nv_bfloat16 *p_ah, *p_al, *p_bh, *p_bl;
    cudaGetSymbolAddress((void**)&p_feats, g_feats);
    cudaGetSymbolAddress((void**)&p_zx,    g_zx);
    cudaGetSymbolAddress((void**)&p_y,     g_y);
    cudaGetSymbolAddress((void**)&p_ah,    g_ah);
    cudaGetSymbolAddress((void**)&p_al,    g_al);
    cudaGetSymbolAddress((void**)&p_bh,    g_bh);
    cudaGetSymbolAddress((void**)&p_bl,    g_bl);

    const int ds_smem    = (DMODEL*48 + 16*48) * 4;
    const int chunk_smem = (2*128*65 + 2*128*128 + 3*128) * 4;
    const int ic_smem    = (2*128*65 + 128) * 4;
    const int mma_smem   = 2 * 65536;   // 131072
    cudaFuncSetAttribute(downsample_kernel, cudaFuncAttributeMaxDynamicSharedMemorySize, ds_smem);
    cudaFuncSetAttribute(chunk_kernel,      cudaFuncAttributeMaxDynamicSharedMemorySize, chunk_smem);
    cudaFuncSetAttribute(interchunk_kernel, cudaFuncAttributeMaxDynamicSharedMemorySize, ic_smem);
    cudaFuncSetAttribute(mma_gemm,          cudaFuncAttributeMaxDynamicSharedMemorySize, mma_smem);

    const int M = 2*B_*L_;   // 65536

    // 1. downsample
    downsample_kernel<<<2*B_*HO*(WO/16), 256, ds_smem>>>(left, right, dw, db);

    // 2. in_proj via mma.sync split-bf16
    {
        size_t n4 = (size_t)M * DMODEL / 4;
        cvt_split4<<<(unsigned)((n4 + 255)/256), 256>>>(p_feats, p_ah, p_al, n4);
        size_t nb = (size_t)DPROJ_PAD * DMODEL;
        cvt_split_pad<<<(unsigned)((nb + 255)/256), 256>>>(inpw, p_bh, p_bl, DPROJ, DMODEL, DPROJ_PAD);
        dim3 grid(DPROJ_PAD/128, M/128);
        mma_gemm<<<grid, 256, mma_smem>>>(p_ah, p_al, p_bh, p_bl, p_zx, M, DPROJ, DMODEL);
    }

    // 3-5. conv / dt / cumsum
    {
        size_t tot4 = (size_t)M*CONVD/4;
        conv_split_kernel<<<(unsigned)((tot4 + 255)/256), 256>>>(cw, cb);
    }
    {
        size_t tot = (size_t)M*NH;
        dt_kernel<<<(unsigned)((tot + 255)/256), 256>>>(dtb);
    }
    cum_kernel<<<(2*B_*NC*NH + 255)/256, 256>>>(alog);

    // 6-8. SSD
    chunk_kernel<<<2*B_*NC*NH, 256, chunk_smem>>>(Dv);
    scan_kernel<<<2*B_*NH, 256>>>();
    interchunk_kernel<<<2*B_*NC*NH, 256, ic_smem>>>();

    // 9. rmsnorm
    rmsnorm_kernel<<<M, 128>>>(nw);

    // 10. out_proj via mma.sync split-bf16
    {
        size_t n4 = (size_t)M * DINNER / 4;
        cvt_split4<<<(unsigned)((n4 + 255)/256), 256>>>(p_y, p_ah, p_al, n4);
        size_t nb = (size_t)DMODEL * DINNER;
        cvt_split_pad<<<(unsigned)((nb + 255)/256), 256>>>(outw, p_bh, p_bl, DMODEL, DINNER, DMODEL);
        dim3 grid(DMODEL/128, M/128);
        mma_gemm<<<grid, 256, mma_smem>>>(p_ah, p_al, p_bh, p_bl, out, M, DMODEL, DINNER);
    }
}

// round 5
// speedup vs baseline: 2.7446x; 1.5862x over previous
#include <cuda_runtime.h>
#include <cuda_bf16.h>
#include <math.h>
#include <stdint.h>

// ---------------- problem constants ----------------
#define B_      4
#define L_      8192
#define DMODEL  256
#define DINNER  512
#define DSTATE  64
#define NH      4
#define HD      128
#define CHUNKSZ 128
#define NC      64
#define CONVD   640
#define DPROJ   1156
#define DPROJ_PAD 1280
#define HIMG    256
#define WIMG    512
#define HO      64
#define WO      128

// ---------------- static scratch ----------------
__device__ float g_feats[(size_t)2*B_*L_*DMODEL];
__device__ float g_zx   [(size_t)2*B_*L_*DPROJ];
__device__ float g_xbc  [(size_t)2*B_*L_*CONVD];
__device__ float g_dt   [(size_t)2*B_*L_*NH];
__device__ float g_cum  [(size_t)2*B_*L_*NH];
__device__ float g_y    [(size_t)2*B_*L_*DINNER];
__device__ float g_state[(size_t)2*B_*NC*NH*HD*DSTATE];
__device__ float g_hprev[(size_t)2*B_*NC*NH*HD*DSTATE];
__device__ __nv_bfloat16 g_ah[(size_t)2*B_*L_*DINNER];
__device__ __nv_bfloat16 g_al[(size_t)2*B_*L_*DINNER];
__device__ __nv_bfloat16 g_bh[(size_t)DPROJ_PAD*DMODEL];
__device__ __nv_bfloat16 g_bl[(size_t)DPROJ_PAD*DMODEL];

// ---------------- mma.sync helpers ----------------
__device__ __forceinline__ uint32_t smem_to_u32(const void* p) {
    uint32_t a;
    asm("{ .reg .u64 t; cvta.to.shared.u64 t, %1; cvt.u32.u64 %0, t; }" : "=r"(a) : "l"(p));
    return a;
}
__device__ __forceinline__ uint32_t swz(uint32_t o) { return o ^ ((o >> 3) & 0x70); }

__device__ __forceinline__ void cp_async16(uint32_t saddr, const void* gptr) {
    asm volatile("cp.async.cg.shared.global [%0], [%1], 16;" :: "r"(saddr), "l"(gptr));
}
#define CP_COMMIT() asm volatile("cp.async.commit_group;" ::: "memory")
#define CP_WAIT(n)  asm volatile("cp.async.wait_group %0;" :: "n"(n) : "memory")

__device__ __forceinline__ void ldsm_x4(uint32_t* r, uint32_t addr) {
    asm volatile("ldmatrix.sync.aligned.m8n8.x4.shared.b16 {%0,%1,%2,%3}, [%4];"
        : "=r"(r[0]), "=r"(r[1]), "=r"(r[2]), "=r"(r[3]) : "r"(addr));
}
__device__ __forceinline__ void ldsm_x2(uint32_t* r, uint32_t addr) {
    asm volatile("ldmatrix.sync.aligned.m8n8.x2.shared.b16 {%0,%1}, [%2];"
        : "=r"(r[0]), "=r"(r[1]) : "r"(addr));
}
__device__ __forceinline__ void mma_bf16(float* c, const uint32_t* a, const uint32_t* b) {
    asm volatile("mma.sync.aligned.m16n8k16.row.col.f32.bf16.bf16.f32 "
        "{%0,%1,%2,%3}, {%4,%5,%6,%7}, {%8,%9}, {%0,%1,%2,%3};"
        : "+f"(c[0]), "+f"(c[1]), "+f"(c[2]), "+f"(c[3])
        : "r"(a[0]), "r"(a[1]), "r"(a[2]), "r"(a[3]), "r"(b[0]), "r"(b[1]));
}
__device__ __forceinline__ void split_bf16(float v, __nv_bfloat16& h, __nv_bfloat16& l) {
    h = __float2bfloat16_rn(v);
    l = __float2bfloat16_rn(v - __bfloat162float(h));
}

// ============================================================================
// split-bf16 tensor GEMM (as round 4, passing)
// ============================================================================
__global__ void __launch_bounds__(256)
mma_gemm(const __nv_bfloat16* __restrict__ Ah, const __nv_bfloat16* __restrict__ Al,
         const __nv_bfloat16* __restrict__ Bh, const __nv_bfloat16* __restrict__ Bl,
         float* __restrict__ C, int M, int N, int K) {
    extern __shared__ char smem[];
    uint32_t sbase = smem_to_u32(smem);
    int tid = threadIdx.x, wid = tid >> 5, lane = tid & 31;
    int m0 = blockIdx.y * 128, n0 = blockIdx.x * 128;
    int wm = wid & 3, wn = wid >> 2;

    float acc[2][8][4];
    #pragma unroll
    for (int mt = 0; mt < 2; mt++)
        #pragma unroll
        for (int nt = 0; nt < 8; nt++)
            #pragma unroll
            for (int q = 0; q < 4; q++) acc[mt][nt][q] = 0.f;

    const int KT = K >> 6;
    int lrow = tid >> 3, lc8 = tid & 7;

    auto issue = [&](int kt) {
        uint32_t so = (uint32_t)(kt & 1) << 16;
        #pragma unroll
        for (int u = 0; u < 4; u++) {
            int row = lrow + 32 * u;
            uint32_t sw = swz((uint32_t)row * 128 + lc8 * 16);
            size_t aoff = ((size_t)(m0 + row) * K + kt * 64 + lc8 * 8);
            size_t boff = ((size_t)(n0 + row) * K + kt * 64 + lc8 * 8);
            cp_async16(sbase + so + sw,         Ah + aoff);
            cp_async16(sbase + so + 16384 + sw, Al + aoff);
            cp_async16(sbase + so + 32768 + sw, Bh + boff);
            cp_async16(sbase + so + 49152 + sw, Bl + boff);
        }
        CP_COMMIT();
    };

    issue(0);

    for (int kt = 0; kt < KT; kt++) {
        bool has_next = (kt + 1 < KT);
        if (has_next) { issue(kt + 1); CP_WAIT(1); }
        else          { CP_WAIT(0); }
        __syncthreads();

        uint32_t so = (uint32_t)(kt & 1) << 16;
        #pragma unroll
        for (int ks = 0; ks < 4; ks++) {
            uint32_t ah[2][4], alr[2][4];
            #pragma unroll
            for (int mt = 0; mt < 2; mt++) {
                int row = wm * 32 + mt * 16 + (lane & 15);
                int kb  = ks * 32 + ((lane >> 4) << 4);
                uint32_t off = swz((uint32_t)row * 128 + kb);
                ldsm_x4(ah[mt],  sbase + so + off);
                ldsm_x4(alr[mt], sbase + so + 16384 + off);
            }
            int l2 = lane & 15;
            int nrow = wn * 64 + (l2 & 7);
            int kb2  = ks * 32 + ((l2 >> 3) << 4);
            #pragma unroll
            for (int nt = 0; nt < 8; nt++) {
                uint32_t bh[2], bl[2];
                uint32_t off = swz((uint32_t)(nrow + nt * 8) * 128 + kb2);
                ldsm_x2(bh, sbase + so + 32768 + off);
                ldsm_x2(bl, sbase + so + 49152 + off);
                #pragma unroll
                for (int mt = 0; mt < 2; mt++) {
                    mma_bf16(acc[mt][nt], ah[mt],  bh);
                    mma_bf16(acc[mt][nt], ah[mt],  bl);
                    mma_bf16(acc[mt][nt], alr[mt], bh);
                }
            }
        }
        __syncthreads();
    }

    int r_base = m0 + wm * 32 + (lane >> 2);
    int c_base = n0 + wn * 64 + 2 * (lane & 3);
    #pragma unroll
    for (int mt = 0; mt < 2; mt++) {
        #pragma unroll
        for (int nt = 0; nt < 8; nt++) {
            int c = c_base + nt * 8;
            if (c < N) {
                int r = r_base + mt * 16;
                *(float2*)&C[(size_t)r * N + c]       = make_float2(acc[mt][nt][0], acc[mt][nt][1]);
                *(float2*)&C[(size_t)(r + 8) * N + c] = make_float2(acc[mt][nt][2], acc[mt][nt][3]);
            }
        }
    }
}

// ============================================================================
// conversions
// ============================================================================
__global__ void cvt_split4(const float* __restrict__ src,
                           __nv_bfloat16* __restrict__ hi,
                           __nv_bfloat16* __restrict__ lo, size_t n4) {
    size_t i = (size_t)blockIdx.x * 256 + threadIdx.x;
    if (i >= n4) return;
    float4 v = *(const float4*)(src + i * 4);
    __nv_bfloat16 h0, h1, h2, h3, l0, l1, l2, l3;
    split_bf16(v.x, h0, l0); split_bf16(v.y, h1, l1);
    split_bf16(v.z, h2, l2); split_bf16(v.w, h3, l3);
    *(__nv_bfloat162*)(hi + i*4)     = __nv_bfloat162(h0, h1);
    *(__nv_bfloat162*)(hi + i*4 + 2) = __nv_bfloat162(h2, h3);
    *(__nv_bfloat162*)(lo + i*4)     = __nv_bfloat162(l0, l1);
    *(__nv_bfloat162*)(lo + i*4 + 2) = __nv_bfloat162(l2, l3);
}

__global__ void cvt_split_pad(const float* __restrict__ src,
                              __nv_bfloat16* __restrict__ hi,
                              __nv_bfloat16* __restrict__ lo,
                              int N, int K, int Npad) {
    size_t i = (size_t)blockIdx.x * 256 + threadIdx.x;
    if (i >= (size_t)Npad * K) return;
    int n = (int)(i / K);
    float v = (n < N) ? src[i] : 0.f;
    __nv_bfloat16 h, l; split_bf16(v, h, l);
    hi[i] = h; lo[i] = l;
}

// ============================================================================
// 1. Downsample conv
// ============================================================================
__global__ void downsample_kernel(const float* __restrict__ left,
                                  const float* __restrict__ right,
                                  const float* __restrict__ dw,
                                  const float* __restrict__ db) {
    extern __shared__ float sm[];
    float* sw = sm;
    float* sp = sm + DMODEL*48;
    int bi = blockIdx.x;
    int wt = bi % (WO/16);
    int oh = (bi / (WO/16)) % HO;
    int b  = (bi / (WO/16 * HO)) % B_;
    int s  = bi / (WO/16 * HO * B_);
    const float* img = s ? right : left;
    int tid = threadIdx.x;
    for (int i = tid; i < DMODEL*48; i += 256) sw[i] = dw[i];
    int ow0 = wt * 16;
    for (int i = tid; i < 16*48; i += 256) {
        int pos = i / 48, j = i % 48;
        int ci = j / 16, kh = (j % 16) / 4, kw = j % 4;
        sp[i] = img[((size_t)(b*3 + ci)*HIMG + (oh*4 + kh))*WIMG + (ow0 + pos)*4 + kw];
    }
    __syncthreads();
    int c = tid;
    float bias = db[c];
    for (int pos = 0; pos < 16; pos++) {
        float acc = bias;
        #pragma unroll
        for (int j = 0; j < 48; j++) acc += sp[pos*48 + j] * sw[c*48 + j];
        int l = oh*WO + ow0 + pos;
        g_feats[((size_t)(s*B_ + b)*L_ + l)*DMODEL + c] = acc;
    }
}

// ============================================================================
// 3. conv1d + split
// ============================================================================
__global__ void conv_split_kernel(const float* __restrict__ cw,
                                  const float* __restrict__ cb) {
    size_t idx = (size_t)blockIdx.x * 256 + threadIdx.x;
    size_t total4 = (size_t)2*B_*L_*CONVD/4;
    if (idx >= total4) return;
    int c4 = (int)(idx % (CONVD/4));
    size_t t = idx / (CONVD/4);
    int l  = (int)(t % L_);
    int sb = (int)(t / L_);
    int ch = c4 * 4;
    float4 out;
    if (sb < B_) {
        float acc[4] = {cb[ch], cb[ch+1], cb[ch+2], cb[ch+3]};
        #pragma unroll
        for (int k = 0; k < 4; k++) {
            int ls = l + k - 3;
            if (ls >= 0) {
                float4 v = *(const float4*)&g_zx[((size_t)sb*L_ + ls)*DPROJ + 512 + ch];
                acc[0] += cw[(ch+0)*4 + k] * v.x;
                acc[1] += cw[(ch+1)*4 + k] * v.y;
                acc[2] += cw[(ch+2)*4 + k] * v.z;
                acc[3] += cw[(ch+3)*4 + k] * v.w;
            }
        }
        out.x = acc[0] / (1.f + __expf(-acc[0]));
        out.y = acc[1] / (1.f + __expf(-acc[1]));
        out.z = acc[2] / (1.f + __expf(-acc[2]));
        out.w = acc[3] / (1.f + __expf(-acc[3]));
    } else {
        out = *(const float4*)&g_zx[((size_t)sb*L_ + l)*DPROJ + 512 + ch];
    }
    *(float4*)&g_xbc[((size_t)sb*L_ + l)*CONVD + ch] = out;
}

// ============================================================================
// 4. dt softplus
// ============================================================================
__global__ void dt_kernel(const float* __restrict__ dt_bias) {
    size_t idx = (size_t)blockIdx.x * 256 + threadIdx.x;
    if (idx >= (size_t)2*B_*L_*NH) return;
    int h = (int)(idx % NH);
    size_t row = idx / NH;
    float v = g_zx[row*DPROJ + (DINNER + CONVD) + h] + dt_bias[h];
    g_dt[idx] = (v > 20.f) ? v : log1pf(__expf(v));
}

// ============================================================================
// 5. per-chunk cumsum (warp-parallel): one warp per (sb,c,h)
// ============================================================================
__global__ void cum_kernel_v2(const float* __restrict__ A_log) {
    int gw = blockIdx.x * 8 + (threadIdx.x >> 5);   // 2048 warps
    int lane = threadIdx.x & 31;
    if (gw >= 2*B_*NC*NH) return;
    int h = gw % NH;
    int c = (gw / NH) % NC;
    int sb = gw / (NH * NC);
    float An = -__expf(A_log[h]);
    size_t base = ((size_t)sb*L_ + c*CHUNKSZ + lane*4)*NH + h;
    float v0 = g_dt[base], v1 = g_dt[base + NH], v2 = g_dt[base + 2*NH], v3 = g_dt[base + 3*NH];
    float p0 = v0, p1 = p0 + v1, p2 = p1 + v2, p3 = p2 + v3;
    float incl = p3;
    #pragma unroll
    for (int o = 1; o < 32; o <<= 1) {
        float t = __shfl_up_sync(0xFFFFFFFFu, incl, o);
        if (lane >= o) incl += t;
    }
    float ex = incl - p3;
    g_cum[base]        = An * (ex + p0);
    g_cum[base + NH]   = An * (ex + p1);
    g_cum[base + 2*NH] = An * (ex + p2);
    g_cum[base + 3*NH] = An * (ex + p3);
}

// ============================================================================
// 6. Intra-chunk SSD via tensor cores (split-bf16, 3-pass).
//    One block per (s,b,c,h), 256 threads (8 warps, 4x2).
//    smem (bytes):
//      cum 0..512, dts 512..1024, wj 1024..1536, pad to 2048
//      XT  hi: 2048 + pan*16384 (pan 0,1)  lo: 2048+32768+pan*16384   (X^T [p][j])
//      BW  hi: 67584 + pan*8192           lo: 67584+16384+pan*8192   ((w*B)^T [n][j])
//      R1 = 100352: phase A: Ch/Cl/Bh/Bl (+0/+16384/+32768/+49152)
//                   phase B: Gh pan*16384, Gl 32768+pan*16384
//    total 165888
// ============================================================================
#define CK_XT_H(p) (2048u + (uint32_t)(p)*16384u)
#define CK_XT_L(p) (34816u + (uint32_t)(p)*16384u)
#define CK_BW_H(p) (67584u + (uint32_t)(p)*8192u)
#define CK_BW_L(p) (83968u + (uint32_t)(p)*8192u)
#define CK_R1      100352u
#define CK_GH(p)   (CK_R1 + (uint32_t)(p)*16384u)
#define CK_GL(p)   (CK_R1 + 32768u + (uint32_t)(p)*16384u)
#define CK_SMEM    165888

__global__ void __launch_bounds__(256)
chunk_kernel_v2(const float* __restrict__ Dv) {
    extern __shared__ char smraw[];
    uint32_t sbase = smem_to_u32(smraw);
    float* cum_s = (float*)smraw;
    float* dts_s = (float*)(smraw + 512);
    float* wj_s  = (float*)(smraw + 1024);

    int bi = blockIdx.x, tid = threadIdx.x;
    int wid = tid >> 5, lane = tid & 31;
    int wm = wid & 3, wn = wid >> 2;
    int l2 = lane & 15;
    int h  = bi % NH;
    int c  = (bi / NH) % NC;
    int b  = (bi / (NH*NC)) % B_;
    int s  = bi / (NH*NC*B_);
    int sb  = s*B_ + b;
    int sbo = (1 - s)*B_ + b;
    size_t l0 = (size_t)c * CHUNKSZ;

    if (tid < 128) {
        size_t off = ((size_t)sb*L_ + l0 + tid)*NH + h;
        cum_s[tid] = g_cum[off];
        dts_s[tid] = g_dt[off];
    }
    __syncthreads();
    if (tid < 128) wj_s[tid] = dts_s[tid] * __expf(cum_s[127] - cum_s[tid]);
    __syncthreads();

    // ---- loads: C,B (8192 each), Bw^T, X^T (16384) with bf16 split ----
    for (int idx = tid; idx < 128*64; idx += 256) {
        int j = idx >> 6, n = idx & 63;
        float cv = g_xbc[((size_t)sb *L_ + l0 + j)*CONVD + 576 + n];
        float bv = g_xbc[((size_t)sbo*L_ + l0 + j)*CONVD + 512 + n];
        __nv_bfloat16 hh, ll;
        uint32_t so = swz((uint32_t)j*128 + n*2);
        split_bf16(cv, hh, ll);
        *(__nv_bfloat16*)(smraw + CK_R1 + so)         = hh;
        *(__nv_bfloat16*)(smraw + CK_R1 + 16384 + so) = ll;
        split_bf16(bv, hh, ll);
        *(__nv_bfloat16*)(smraw + CK_R1 + 32768 + so) = hh;
        *(__nv_bfloat16*)(smraw + CK_R1 + 49152 + so) = ll;
        // Bw^T: (w*B) at [n][j]
        float bw = bv * wj_s[j];
        split_bf16(bw, hh, ll);
        uint32_t st = swz((uint32_t)n*128 + (j & 63)*2);
        int pan = j >> 6;
        *(__nv_bfloat16*)(smraw + CK_BW_H(pan) + st) = hh;
        *(__nv_bfloat16*)(smraw + CK_BW_L(pan) + st) = ll;
    }
    for (int idx = tid; idx < 128*128; idx += 256) {
        int j = idx >> 7, p = idx & 127;
        float xv = g_xbc[((size_t)sbo*L_ + l0 + j)*CONVD + h*HD + p];
        __nv_bfloat16 hh, ll; split_bf16(xv, hh, ll);
        int pan = j >> 6;
        uint32_t st = swz((uint32_t)p*128 + (j & 63)*2);
        *(__nv_bfloat16*)(smraw + CK_XT_H(pan) + st) = hh;
        *(__nv_bfloat16*)(smraw + CK_XT_L(pan) + st) = ll;
    }
    __syncthreads();

    // ---- phase A: G = C * B^T  (M=i 128, N=j 128, K=n 64) ----
    float accg[2][8][4];
    #pragma unroll
    for (int mt = 0; mt < 2; mt++)
        #pragma unroll
        for (int nt = 0; nt < 8; nt++)
            #pragma unroll
            for (int q = 0; q < 4; q++) accg[mt][nt][q] = 0.f;
    #pragma unroll
    for (int ks = 0; ks < 4; ks++) {
        uint32_t ah[2][4], al[2][4];
        #pragma unroll
        for (int mt = 0; mt < 2; mt++) {
            int row = wm*32 + mt*16 + (lane & 15);
            uint32_t off = swz((uint32_t)row*128 + ks*32 + ((lane >> 4) << 4));
            ldsm_x4(ah[mt], sbase + CK_R1 + off);
            ldsm_x4(al[mt], sbase + CK_R1 + 16384 + off);
        }
        #pragma unroll
        for (int nt = 0; nt < 8; nt++) {
            int row = wn*64 + nt*8 + (l2 & 7);
            uint32_t off = swz((uint32_t)row*128 + ks*32 + ((l2 >> 3) << 4));
            uint32_t bh[2], bl[2];
            ldsm_x2(bh, sbase + CK_R1 + 32768 + off);
            ldsm_x2(bl, sbase + CK_R1 + 49152 + off);
            #pragma unroll
            for (int mt = 0; mt < 2; mt++) {
                mma_bf16(accg[mt][nt], ah[mt], bh);
                mma_bf16(accg[mt][nt], ah[mt], bl);
                mma_bf16(accg[mt][nt], al[mt], bh);
            }
        }
    }
    __syncthreads();   // done reading C/B before overwriting with G

    // mask * exp(cum_i - cum_j) * dt_j, re-stage as bf16 panels (panel = wn)
    {
        int r0 = lane >> 2, cj = 2*(lane & 3);
        #pragma unroll
        for (int mt = 0; mt < 2; mt++) {
            #pragma unroll
            for (int nt = 0; nt < 8; nt++) {
                int j0 = wn*64 + nt*8 + cj;
                int jl = (j0 & 63);
                #pragma unroll
                for (int half = 0; half < 2; half++) {
                    int i = wm*32 + mt*16 + r0 + half*8;
                    float ci = cum_s[i];
                    float g0 = (j0   <= i) ? accg[mt][nt][half*2]   * __expf(ci - cum_s[j0])   * dts_s[j0]   : 0.f;
                    float g1 = (j0+1 <= i) ? accg[mt][nt][half*2+1] * __expf(ci - cum_s[j0+1]) * dts_s[j0+1] : 0.f;
                    __nv_bfloat16 h0, l0b, h1, l1b;
                    split_bf16(g0, h0, l0b); split_bf16(g1, h1, l1b);
                    uint32_t st = swz((uint32_t)i*128 + jl*2);
                    *(__nv_bfloat162*)(smraw + CK_GH(wn) + st) = __nv_bfloat162(h0, h1);
                    *(__nv_bfloat162*)(smraw + CK_GL(wn) + st) = __nv_bfloat162(l0b, l1b);
                }
            }
        }
    }
    __syncthreads();

    // ---- phase B: Y = G @ X  (M=i, N=p 128, K=j 128) ----
    {
        float accy[2][8][4];
        #pragma unroll
        for (int mt = 0; mt < 2; mt++)
            #pragma unroll
            for (int nt = 0; nt < 8; nt++)
                #pragma unroll
                for (int q = 0; q < 4; q++) accy[mt][nt][q] = 0.f;
        #pragma unroll
        for (int pan = 0; pan < 2; pan++) {
            #pragma unroll
            for (int ks = 0; ks < 4; ks++) {
                uint32_t gh[2][4], gl[2][4];
                #pragma unroll
                for (int mt = 0; mt < 2; mt++) {
                    int row = wm*32 + mt*16 + (lane & 15);
                    uint32_t off = swz((uint32_t)row*128 + ks*32 + ((lane >> 4) << 4));
                    ldsm_x4(gh[mt], sbase + CK_GH(pan) + off);
                    ldsm_x4(gl[mt], sbase + CK_GL(pan) + off);
                }
                #pragma unroll
                for (int nt = 0; nt < 8; nt++) {
                    int row = wn*64 + nt*8 + (l2 & 7);
                    uint32_t off = swz((uint32_t)row*128 + ks*32 + ((l2 >> 3) << 4));
                    uint32_t xh[2], xl[2];
                    ldsm_x2(xh, sbase + CK_XT_H(pan) + off);
                    ldsm_x2(xl, sbase + CK_XT_L(pan) + off);
                    #pragma unroll
                    for (int mt = 0; mt < 2; mt++) {
                        mma_bf16(accy[mt][nt], gh[mt], xh);
                        mma_bf16(accy[mt][nt], gh[mt], xl);
                        mma_bf16(accy[mt][nt], gl[mt], xh);
                    }
                }
            }
        }
        // epilogue: + D*x, write g_y
        float Dh = Dv[h];
        int r0 = lane >> 2, cp = 2*(lane & 3);
        #pragma unroll
        for (int mt = 0; mt < 2; mt++) {
            #pragma unroll
            for (int nt = 0; nt < 8; nt++) {
                int p0 = wn*64 + nt*8 + cp;
                #pragma unroll
                for (int half = 0; half < 2; half++) {
                    int i = wm*32 + mt*16 + r0 + half*8;
                    int ipan = i >> 6;
                    uint32_t b0 = swz((uint32_t)p0*128 + (i & 63)*2);
                    uint32_t b1 = swz((uint32_t)(p0+1)*128 + (i & 63)*2);
                    float x0 = __bfloat162float(*(__nv_bfloat16*)(smraw + CK_XT_H(ipan) + b0))
                             + __bfloat162float(*(__nv_bfloat16*)(smraw + CK_XT_L(ipan) + b0));
                    float x1 = __bfloat162float(*(__nv_bfloat16*)(smraw + CK_XT_H(ipan) + b1))
                             + __bfloat162float(*(__nv_bfloat16*)(smraw + CK_XT_L(ipan) + b1));
                    size_t off = ((size_t)sb*L_ + l0 + i)*DINNER + h*HD + p0;
                    *(float2*)&g_y[off] = make_float2(accy[mt][nt][half*2] + Dh*x0,
                                                      accy[mt][nt][half*2+1] + Dh*x1);
                }
            }
        }
    }

    // ---- phase C: S[p][n] = sum_j X^T[p][j] * Bw^T[n][j]  (M=p 128, N=n 64, K=j 128) ----
    {
        float accs[2][4][4];
        #pragma unroll
        for (int mt = 0; mt < 2; mt++)
            #pragma unroll
            for (int nt = 0; nt < 4; nt++)
                #pragma unroll
                for (int q = 0; q < 4; q++) accs[mt][nt][q] = 0.f;
        #pragma unroll
        for (int pan = 0; pan < 2; pan++) {
            #pragma unroll
            for (int ks = 0; ks < 4; ks++) {
                uint32_t xh[2][4], xl[2][4];
                #pragma unroll
                for (int mt = 0; mt < 2; mt++) {
                    int row = wm*32 + mt*16 + (lane & 15);
                    uint32_t off = swz((uint32_t)row*128 + ks*32 + ((lane >> 4) << 4));
                    ldsm_x4(xh[mt], sbase + CK_XT_H(pan) + off);
                    ldsm_x4(xl[mt], sbase + CK_XT_L(pan) + off);
                }
                #pragma unroll
                for (int nt = 0; nt < 4; nt++) {
                    int row = wn*32 + nt*8 + (l2 & 7);
                    uint32_t off = swz((uint32_t)row*128 + ks*32 + ((l2 >> 3) << 4));
                    uint32_t bwh[2], bwl[2];
                    ldsm_x2(bwh, sbase + CK_BW_H(pan) + off);
                    ldsm_x2(bwl, sbase + CK_BW_L(pan) + off);
                    #pragma unroll
                    for (int mt = 0; mt < 2; mt++) {
                        mma_bf16(accs[mt][nt], xh[mt], bwh);
                        mma_bf16(accs[mt][nt], xh[mt], bwl);
                        mma_bf16(accs[mt][nt], xl[mt], bwh);
                    }
                }
            }
        }
        size_t sb0 = (size_t)bi * (HD*DSTATE);
        int r0 = lane >> 2, cn = 2*(lane & 3);
        #pragma unroll
        for (int mt = 0; mt < 2; mt++) {
            #pragma unroll
            for (int nt = 0; nt < 4; nt++) {
                int n0 = wn*32 + nt*8 + cn;
                #pragma unroll
                for (int half = 0; half < 2; half++) {
                    int p = wm*32 + mt*16 + r0 + half*8;
                    *(float2*)&g_state[sb0 + (size_t)p*64 + n0] =
                        make_float2(accs[mt][nt][half*2], accs[mt][nt][half*2+1]);
                }
            }
        }
    }
}

// ============================================================================
// 7. Inter-chunk scan (parallelized: 8 segments per (sb,h))
// ============================================================================
__global__ void scan_kernel_v2() {
    int t   = blockIdx.x >> 3;       // (sb,h)
    int seg = blockIdx.x & 7;
    int h = t % NH;
    int sb = t / NH;
    int off0 = seg * 1024 + threadIdx.x * 4;
    float4 hreg = make_float4(0.f, 0.f, 0.f, 0.f);
    for (int c = 0; c < NC; c++) {
        float dec = __expf(g_cum[((size_t)sb*L_ + c*CHUNKSZ + 127)*NH + h]);
        size_t o = (((size_t)sb*NC + c)*NH + h) * (HD*DSTATE) + off0;
        *(float4*)&g_hprev[o] = hreg;
        float4 st = *(const float4*)&g_state[o];
        hreg.x = hreg.x*dec + st.x;
        hreg.y = hreg.y*dec + st.y;
        hreg.z = hreg.z*dec + st.z;
        hreg.w = hreg.w*dec + st.w;
    }
}

// ============================================================================
// 8. Inter-chunk contribution via tensor cores:
//    y[i][p] += exp(cum_i) * sum_n C[i][n] * H[p][n]   (M=128, N=128, K=64)
//    smem: cum 0..512, pad 1024; Ch 1024, Cl +16384, Hh +32768, Hl +49152; total 66560
// ============================================================================
__global__ void __launch_bounds__(256)
interchunk_kernel_v2() {
    extern __shared__ char smraw[];
    uint32_t sbase = smem_to_u32(smraw);
    float* cum_s = (float*)smraw;

    int bi = blockIdx.x, tid = threadIdx.x;
    int wid = tid >> 5, lane = tid & 31;
    int wm = wid & 3, wn = wid >> 2;
    int l2 = lane & 15;
    int h  = bi % NH;
    int c  = (bi / NH) % NC;
    int b  = (bi / (NH*NC)) % B_;
    int s  = bi / (NH*NC*B_);
    int sb = s*B_ + b;
    size_t l0 = (size_t)c * CHUNKSZ;
    size_t hbase = (size_t)bi * (HD*DSTATE);

    if (tid < 128) cum_s[tid] = g_cum[((size_t)sb*L_ + l0 + tid)*NH + h];

    for (int idx = tid; idx < 128*64; idx += 256) {
        int r = idx >> 6, n = idx & 63;
        float cv = g_xbc[((size_t)sb*L_ + l0 + r)*CONVD + 576 + n];
        float hv = g_hprev[hbase + idx];
        __nv_bfloat16 hh, ll;
        uint32_t so = swz((uint32_t)r*128 + n*2);
        split_bf16(cv, hh, ll);
        *(__nv_bfloat16*)(smraw + 1024 + so)         = hh;
        *(__nv_bfloat16*)(smraw + 1024 + 16384 + so) = ll;
        split_bf16(hv, hh, ll);
        *(__nv_bfloat16*)(smraw + 1024 + 32768 + so) = hh;
        *(__nv_bfloat16*)(smraw + 1024 + 49152 + so) = ll;
    }
    __syncthreads();

    float acc[2][8][4];
    #pragma unroll
    for (int mt = 0; mt < 2; mt++)
        #pragma unroll
        for (int nt = 0; nt < 8; nt++)
            #pragma unroll
            for (int q = 0; q < 4; q++) acc[mt][nt][q] = 0.f;
    #pragma unroll
    for (int ks = 0; ks < 4; ks++) {
        uint32_t ah[2][4], al[2][4];
        #pragma unroll
        for (int mt = 0; mt < 2; mt++) {
            int row = wm*32 + mt*16 + (lane & 15);
            uint32_t off = swz((uint32_t)row*128 + ks*32 + ((lane >> 4) << 4));
            ldsm_x4(ah[mt], sbase + 1024 + off);
            ldsm_x4(al[mt], sbase + 1024 + 16384 + off);
        }
        #pragma unroll
        for (int nt = 0; nt < 8; nt++) {
            int row = wn*64 + nt*8 + (l2 & 7);
            uint32_t off = swz((uint32_t)row*128 + ks*32 + ((l2 >> 3) << 4));
            uint32_t hh[2], hl[2];
            ldsm_x2(hh, sbase + 1024 + 32768 + off);
            ldsm_x2(hl, sbase + 1024 + 49152 + off);
            #pragma unroll
            for (int mt = 0; mt < 2; mt++) {
                mma_bf16(acc[mt][nt], ah[mt], hh);
                mma_bf16(acc[mt][nt], ah[mt], hl);
                mma_bf16(acc[mt][nt], al[mt], hh);
            }
        }
    }

    int r0 = lane >> 2, cp = 2*(lane & 3);
    #pragma unroll
    for (int mt = 0; mt < 2; mt++) {
        #pragma unroll
        for (int nt = 0; nt < 8; nt++) {
            int p = wn*64 + nt*8 + cp;
            #pragma unroll
            for (int half = 0; half < 2; half++) {
                int i = wm*32 + mt*16 + r0 + half*8;
                float sc = __expf(cum_s[i]);
                size_t off = ((size_t)sb*L_ + l0 + i)*DINNER + h*HD + p;
                float2 v = *(float2*)&g_y[off];
                v.x += sc * acc[mt][nt][half*2];
                v.y += sc * acc[mt][nt][half*2+1];
                *(float2*)&g_y[off] = v;
            }
        }
    }
}

// ============================================================================
// 9. Gated RMSNorm (in place)
// ============================================================================
__global__ void rmsnorm_kernel(const float* __restrict__ norm_w) {
    int row = blockIdx.x;
    int tid = threadIdx.x;
    __shared__ float red[4];
    size_t ybase = (size_t)row * DINNER;
    size_t zbase = (size_t)row * DPROJ;
    float g[4];
    float ss = 0.f;
    #pragma unroll
    for (int t = 0; t < 4; t++) {
        int d = tid + 128*t;
        float z = g_zx[zbase + d];
        float yv = g_y[ybase + d];
        float gg = yv * (z / (1.f + __expf(-z)));
        g[t] = gg;
        ss += gg*gg;
    }
    #pragma unroll
    for (int o = 16; o > 0; o >>= 1) ss += __shfl_xor_sync(0xFFFFFFFFu, ss, o);
    if ((tid & 31) == 0) red[tid >> 5] = ss;
    __syncthreads();
    float tot = red[0] + red[1] + red[2] + red[3];
    float scale = rsqrtf(tot / (float)DINNER + 1e-5f);
    #pragma unroll
    for (int t = 0; t < 4; t++) {
        int d = tid + 128*t;
        g_y[ybase + d] = g[t] * scale * norm_w[d];
    }
}

// ============================================================================
extern "C" void kernel_launch(void* const* d_in, const int* in_sizes, int n_in,
                              void* d_out, int out_size) {
    const float* left   = (const float*)d_in[0];
    const float* right  = (const float*)d_in[1];
    const float* dw     = (const float*)d_in[2];
    const float* db     = (const float*)d_in[3];
    const float* inpw   = (const float*)d_in[4];
    const float* cw     = (const float*)d_in[5];
    const float* cb     = (const float*)d_in[6];
    const float* dtb    = (const float*)d_in[7];
    const float* alog   = (const float*)d_in[8];
    const float* Dv     = (const float*)d_in[9];
    const float* nw     = (const float*)d_in[10];
    const float* outw   = (const float*)d_in[11];
    float* out          = (float*)d_out;

    float *p_feats, *p_zx, *p_y;
    __nv_bfloat16 *p_ah, *p_al, *p_bh, *p_bl;
    cudaGetSymbolAddress((void**)&p_feats, g_feats);
    cudaGetSymbolAddress((void**)&p_zx,    g_zx);
    cudaGetSymbolAddress((void**)&p_y,     g_y);
    cudaGetSymbolAddress((void**)&p_ah,    g_ah);
    cudaGetSymbolAddress((void**)&p_al,    g_al);
    cudaGetSymbolAddress((void**)&p_bh,    g_bh);
    cudaGetSymbolAddress((void**)&p_bl,    g_bl);

    const int ds_smem  = (DMODEL*48 + 16*48) * 4;
    const int mma_smem = 2 * 65536;
    const int ic_smem  = 66560;
    cudaFuncSetAttribute(downsample_kernel,    cudaFuncAttributeMaxDynamicSharedMemorySize, ds_smem);
    cudaFuncSetAttribute(mma_gemm,             cudaFuncAttributeMaxDynamicSharedMemorySize, mma_smem);
    cudaFuncSetAttribute(chunk_kernel_v2,      cudaFuncAttributeMaxDynamicSharedMemorySize, CK_SMEM);
    cudaFuncSetAttribute(interchunk_kernel_v2, cudaFuncAttributeMaxDynamicSharedMemorySize, ic_smem);

    const int M = 2*B_*L_;   // 65536

    downsample_kernel<<<2*B_*HO*(WO/16), 256, ds_smem>>>(left, right, dw, db);

    // in_proj
    {
        size_t n4 = (size_t)M * DMODEL / 4;
        cvt_split4<<<(unsigned)((n4 + 255)/256), 256>>>(p_feats, p_ah, p_al, n4);
        size_t nb = (size_t)DPROJ_PAD * DMODEL;
        cvt_split_pad<<<(unsigned)((nb + 255)/256), 256>>>(inpw, p_bh, p_bl, DPROJ, DMODEL, DPROJ_PAD);
        dim3 grid(DPROJ_PAD/128, M/128);
        mma_gemm<<<grid, 256, mma_smem>>>(p_ah, p_al, p_bh, p_bl, p_zx, M, DPROJ, DMODEL);
    }

    {
        size_t tot4 = (size_t)M*CONVD/4;
        conv_split_kernel<<<(unsigned)((tot4 + 255)/256), 256>>>(cw, cb);
    }
    {
        size_t tot = (size_t)M*NH;
        dt_kernel<<<(unsigned)((tot + 255)/256), 256>>>(dtb);
    }
    cum_kernel_v2<<<2*B_*NC*NH/8, 256>>>(alog);

    chunk_kernel_v2<<<2*B_*NC*NH, 256, CK_SMEM>>>(Dv);
    scan_kernel_v2<<<2*B_*NH*8, 256>>>();
    interchunk_kernel_v2<<<2*B_*NC*NH, 256, ic_smem>>>();

    rmsnorm_kernel<<<M, 128>>>(nw);

    // out_proj
    {
        size_t n4 = (size_t)M * DINNER / 4;
        cvt_split4<<<(unsigned)((n4 + 255)/256), 256>>>(p_y, p_ah, p_al, n4);
        size_t nb = (size_t)DMODEL * DINNER;
        cvt_split_pad<<<(unsigned)((nb + 255)/256), 256>>>(outw, p_bh, p_bl, DMODEL, DINNER, DMODEL);
        dim3 grid(DMODEL/128, M/128);
        mma_gemm<<<grid, 256, mma_smem>>>(p_ah, p_al, p_bh, p_bl, out, M, DMODEL, DINNER);
    }
}

// round 6
// speedup vs baseline: 2.8656x; 1.0441x over previous
#include <cuda_runtime.h>
#include <cuda_bf16.h>
#include <math.h>
#include <stdint.h>

// ---------------- problem constants ----------------
#define B_      4
#define L_      8192
#define DMODEL  256
#define DINNER  512
#define DSTATE  64
#define NH      4
#define HD      128
#define CHUNKSZ 128
#define NC      64
#define CONVD   640
#define DPROJ   1156
#define DPROJ_PAD 1280
#define HIMG    256
#define WIMG    512
#define HO      64
#define WO      128

// ---------------- static scratch ----------------
__device__ float g_zx   [(size_t)2*B_*L_*DPROJ];
__device__ float g_xbc  [(size_t)2*B_*L_*CONVD];
__device__ float g_dt   [(size_t)2*B_*L_*NH];
__device__ float g_cum  [(size_t)2*B_*L_*NH];
__device__ float g_y    [(size_t)2*B_*L_*DINNER];
__device__ float g_state[(size_t)2*B_*NC*NH*HD*DSTATE];
__device__ float g_hprev[(size_t)2*B_*NC*NH*HD*DSTATE];
__device__ __nv_bfloat16 g_ah[(size_t)2*B_*L_*DINNER];
__device__ __nv_bfloat16 g_al[(size_t)2*B_*L_*DINNER];
__device__ __nv_bfloat16 g_bh[(size_t)DPROJ_PAD*DMODEL];
__device__ __nv_bfloat16 g_bl[(size_t)DPROJ_PAD*DMODEL];

// ---------------- mma.sync helpers ----------------
__device__ __forceinline__ uint32_t smem_to_u32(const void* p) {
    uint32_t a;
    asm("{ .reg .u64 t; cvta.to.shared.u64 t, %1; cvt.u32.u64 %0, t; }" : "=r"(a) : "l"(p));
    return a;
}
__device__ __forceinline__ uint32_t swz(uint32_t o) { return o ^ ((o >> 3) & 0x70); }

__device__ __forceinline__ void cp_async16(uint32_t saddr, const void* gptr) {
    asm volatile("cp.async.cg.shared.global [%0], [%1], 16;" :: "r"(saddr), "l"(gptr));
}
#define CP_COMMIT() asm volatile("cp.async.commit_group;" ::: "memory")
#define CP_WAIT(n)  asm volatile("cp.async.wait_group %0;" :: "n"(n) : "memory")

__device__ __forceinline__ void ldsm_x4(uint32_t* r, uint32_t addr) {
    asm volatile("ldmatrix.sync.aligned.m8n8.x4.shared.b16 {%0,%1,%2,%3}, [%4];"
        : "=r"(r[0]), "=r"(r[1]), "=r"(r[2]), "=r"(r[3]) : "r"(addr));
}
__device__ __forceinline__ void ldsm_x2(uint32_t* r, uint32_t addr) {
    asm volatile("ldmatrix.sync.aligned.m8n8.x2.shared.b16 {%0,%1}, [%2];"
        : "=r"(r[0]), "=r"(r[1]) : "r"(addr));
}
__device__ __forceinline__ void mma_bf16(float* c, const uint32_t* a, const uint32_t* b) {
    asm volatile("mma.sync.aligned.m16n8k16.row.col.f32.bf16.bf16.f32 "
        "{%0,%1,%2,%3}, {%4,%5,%6,%7}, {%8,%9}, {%0,%1,%2,%3};"
        : "+f"(c[0]), "+f"(c[1]), "+f"(c[2]), "+f"(c[3])
        : "r"(a[0]), "r"(a[1]), "r"(a[2]), "r"(a[3]), "r"(b[0]), "r"(b[1]));
}
__device__ __forceinline__ void split_bf16(float v, __nv_bfloat16& h, __nv_bfloat16& l) {
    h = __float2bfloat16_rn(v);
    l = __float2bfloat16_rn(v - __bfloat162float(h));
}

// ============================================================================
// split-bf16 tensor GEMM, 3-stage cp.async pipeline.
// BM=BN=128, BK=64, 256 threads (8 warps 4x2), warp tile 32x64.
// smem: 3 stages x 65536 (Ah +0, Al +16384, Bh +32768, Bl +49152).
// ============================================================================
__global__ void __launch_bounds__(256)
mma_gemm(const __nv_bfloat16* __restrict__ Ah, const __nv_bfloat16* __restrict__ Al,
         const __nv_bfloat16* __restrict__ Bh, const __nv_bfloat16* __restrict__ Bl,
         float* __restrict__ C, int M, int N, int K) {
    extern __shared__ char smem[];
    uint32_t sbase = smem_to_u32(smem);
    int tid = threadIdx.x, wid = tid >> 5, lane = tid & 31;
    int m0 = blockIdx.y * 128, n0 = blockIdx.x * 128;
    int wm = wid & 3, wn = wid >> 2;

    float acc[2][8][4];
    #pragma unroll
    for (int mt = 0; mt < 2; mt++)
        #pragma unroll
        for (int nt = 0; nt < 8; nt++)
            #pragma unroll
            for (int q = 0; q < 4; q++) acc[mt][nt][q] = 0.f;

    const int KT = K >> 6;
    int lrow = tid >> 3, lc8 = tid & 7;

    auto issue = [&](int kt) {
        uint32_t so = (uint32_t)(kt % 3) * 65536u;
        #pragma unroll
        for (int u = 0; u < 4; u++) {
            int row = lrow + 32 * u;
            uint32_t sw = swz((uint32_t)row * 128 + lc8 * 16);
            size_t aoff = ((size_t)(m0 + row) * K + kt * 64 + lc8 * 8);
            size_t boff = ((size_t)(n0 + row) * K + kt * 64 + lc8 * 8);
            cp_async16(sbase + so + sw,         Ah + aoff);
            cp_async16(sbase + so + 16384 + sw, Al + aoff);
            cp_async16(sbase + so + 32768 + sw, Bh + boff);
            cp_async16(sbase + so + 49152 + sw, Bl + boff);
        }
        CP_COMMIT();
    };

    issue(0);
    if (KT > 1) issue(1);

    for (int kt = 0; kt < KT; kt++) {
        if (kt + 1 < KT) CP_WAIT(1); else CP_WAIT(0);
        __syncthreads();
        if (kt + 2 < KT) issue(kt + 2);

        uint32_t so = (uint32_t)(kt % 3) * 65536u;
        #pragma unroll
        for (int ks = 0; ks < 4; ks++) {
            uint32_t ah[2][4], alr[2][4];
            #pragma unroll
            for (int mt = 0; mt < 2; mt++) {
                int row = wm * 32 + mt * 16 + (lane & 15);
                int kb  = ks * 32 + ((lane >> 4) << 4);
                uint32_t off = swz((uint32_t)row * 128 + kb);
                ldsm_x4(ah[mt],  sbase + so + off);
                ldsm_x4(alr[mt], sbase + so + 16384 + off);
            }
            int l2 = lane & 15;
            int nrow = wn * 64 + (l2 & 7);
            int kb2  = ks * 32 + ((l2 >> 3) << 4);
            #pragma unroll
            for (int nt = 0; nt < 8; nt++) {
                uint32_t bh[2], bl[2];
                uint32_t off = swz((uint32_t)(nrow + nt * 8) * 128 + kb2);
                ldsm_x2(bh, sbase + so + 32768 + off);
                ldsm_x2(bl, sbase + so + 49152 + off);
                #pragma unroll
                for (int mt = 0; mt < 2; mt++) {
                    mma_bf16(acc[mt][nt], ah[mt],  bh);
                    mma_bf16(acc[mt][nt], ah[mt],  bl);
                    mma_bf16(acc[mt][nt], alr[mt], bh);
                }
            }
        }
    }

    int r_base = m0 + wm * 32 + (lane >> 2);
    int c_base = n0 + wn * 64 + 2 * (lane & 3);
    #pragma unroll
    for (int mt = 0; mt < 2; mt++) {
        #pragma unroll
        for (int nt = 0; nt < 8; nt++) {
            int c = c_base + nt * 8;
            if (c < N) {
                int r = r_base + mt * 16;
                *(float2*)&C[(size_t)r * N + c]       = make_float2(acc[mt][nt][0], acc[mt][nt][1]);
                *(float2*)&C[(size_t)(r + 8) * N + c] = make_float2(acc[mt][nt][2], acc[mt][nt][3]);
            }
        }
    }
}

// ============================================================================
// weight conversion (with row padding)
// ============================================================================
__global__ void cvt_split_pad(const float* __restrict__ src,
                              __nv_bfloat16* __restrict__ hi,
                              __nv_bfloat16* __restrict__ lo,
                              int N, int K, int Npad) {
    size_t i = (size_t)blockIdx.x * 256 + threadIdx.x;
    if (i >= (size_t)Npad * K) return;
    int n = (int)(i / K);
    float v = (n < N) ? src[i] : 0.f;
    __nv_bfloat16 h, l; split_bf16(v, h, l);
    hi[i] = h; lo[i] = l;
}

// ============================================================================
// 1. Downsample conv -> writes split-bf16 A operand directly
// ============================================================================
__global__ void downsample_kernel(const float* __restrict__ left,
                                  const float* __restrict__ right,
                                  const float* __restrict__ dw,
                                  const float* __restrict__ db) {
    extern __shared__ float sm[];
    float* sw = sm;
    float* sp = sm + DMODEL*48;
    int bi = blockIdx.x;
    int wt = bi % (WO/16);
    int oh = (bi / (WO/16)) % HO;
    int b  = (bi / (WO/16 * HO)) % B_;
    int s  = bi / (WO/16 * HO * B_);
    const float* img = s ? right : left;
    int tid = threadIdx.x;
    for (int i = tid; i < DMODEL*48; i += 256) sw[i] = dw[i];
    int ow0 = wt * 16;
    for (int i = tid; i < 16*48; i += 256) {
        int pos = i / 48, j = i % 48;
        int ci = j / 16, kh = (j % 16) / 4, kw = j % 4;
        sp[i] = img[((size_t)(b*3 + ci)*HIMG + (oh*4 + kh))*WIMG + (ow0 + pos)*4 + kw];
    }
    __syncthreads();
    int c = tid;
    float bias = db[c];
    for (int pos = 0; pos < 16; pos++) {
        float acc = bias;
        #pragma unroll
        for (int j = 0; j < 48; j++) acc += sp[pos*48 + j] * sw[c*48 + j];
        int l = oh*WO + ow0 + pos;
        size_t off = ((size_t)(s*B_ + b)*L_ + l)*DMODEL + c;
        __nv_bfloat16 h, lo; split_bf16(acc, h, lo);
        g_ah[off] = h;
        g_al[off] = lo;
    }
}

// ============================================================================
// 3. conv1d + split
// ============================================================================
__global__ void conv_split_kernel(const float* __restrict__ cw,
                                  const float* __restrict__ cb) {
    size_t idx = (size_t)blockIdx.x * 256 + threadIdx.x;
    size_t total4 = (size_t)2*B_*L_*CONVD/4;
    if (idx >= total4) return;
    int c4 = (int)(idx % (CONVD/4));
    size_t t = idx / (CONVD/4);
    int l  = (int)(t % L_);
    int sb = (int)(t / L_);
    int ch = c4 * 4;
    float4 out;
    if (sb < B_) {
        float acc[4] = {cb[ch], cb[ch+1], cb[ch+2], cb[ch+3]};
        #pragma unroll
        for (int k = 0; k < 4; k++) {
            int ls = l + k - 3;
            if (ls >= 0) {
                float4 v = *(const float4*)&g_zx[((size_t)sb*L_ + ls)*DPROJ + 512 + ch];
                acc[0] += cw[(ch+0)*4 + k] * v.x;
                acc[1] += cw[(ch+1)*4 + k] * v.y;
                acc[2] += cw[(ch+2)*4 + k] * v.z;
                acc[3] += cw[(ch+3)*4 + k] * v.w;
            }
        }
        out.x = acc[0] / (1.f + __expf(-acc[0]));
        out.y = acc[1] / (1.f + __expf(-acc[1]));
        out.z = acc[2] / (1.f + __expf(-acc[2]));
        out.w = acc[3] / (1.f + __expf(-acc[3]));
    } else {
        out = *(const float4*)&g_zx[((size_t)sb*L_ + l)*DPROJ + 512 + ch];
    }
    *(float4*)&g_xbc[((size_t)sb*L_ + l)*CONVD + ch] = out;
}

// ============================================================================
// 4. dt softplus
// ============================================================================
__global__ void dt_kernel(const float* __restrict__ dt_bias) {
    size_t idx = (size_t)blockIdx.x * 256 + threadIdx.x;
    if (idx >= (size_t)2*B_*L_*NH) return;
    int h = (int)(idx % NH);
    size_t row = idx / NH;
    float v = g_zx[row*DPROJ + (DINNER + CONVD) + h] + dt_bias[h];
    g_dt[idx] = (v > 20.f) ? v : log1pf(__expf(v));
}

// ============================================================================
// 5. per-chunk cumsum (warp-parallel)
// ============================================================================
__global__ void cum_kernel_v2(const float* __restrict__ A_log) {
    int gw = blockIdx.x * 8 + (threadIdx.x >> 5);
    int lane = threadIdx.x & 31;
    if (gw >= 2*B_*NC*NH) return;
    int h = gw % NH;
    int c = (gw / NH) % NC;
    int sb = gw / (NH * NC);
    float An = -__expf(A_log[h]);
    size_t base = ((size_t)sb*L_ + c*CHUNKSZ + lane*4)*NH + h;
    float v0 = g_dt[base], v1 = g_dt[base + NH], v2 = g_dt[base + 2*NH], v3 = g_dt[base + 3*NH];
    float p0 = v0, p1 = p0 + v1, p2 = p1 + v2, p3 = p2 + v3;
    float incl = p3;
    #pragma unroll
    for (int o = 1; o < 32; o <<= 1) {
        float t = __shfl_up_sync(0xFFFFFFFFu, incl, o);
        if (lane >= o) incl += t;
    }
    float ex = incl - p3;
    g_cum[base]        = An * (ex + p0);
    g_cum[base + NH]   = An * (ex + p1);
    g_cum[base + 2*NH] = An * (ex + p2);
    g_cum[base + 3*NH] = An * (ex + p3);
}

// ============================================================================
// 6. Intra-chunk SSD via tensor cores (as round 5, passing)
// ============================================================================
#define CK_XT_H(p) (2048u + (uint32_t)(p)*16384u)
#define CK_XT_L(p) (34816u + (uint32_t)(p)*16384u)
#define CK_BW_H(p) (67584u + (uint32_t)(p)*8192u)
#define CK_BW_L(p) (83968u + (uint32_t)(p)*8192u)
#define CK_R1      100352u
#define CK_GH(p)   (CK_R1 + (uint32_t)(p)*16384u)
#define CK_GL(p)   (CK_R1 + 32768u + (uint32_t)(p)*16384u)
#define CK_SMEM    165888

__global__ void __launch_bounds__(256)
chunk_kernel_v2(const float* __restrict__ Dv) {
    extern __shared__ char smraw[];
    uint32_t sbase = smem_to_u32(smraw);
    float* cum_s = (float*)smraw;
    float* dts_s = (float*)(smraw + 512);
    float* wj_s  = (float*)(smraw + 1024);

    int bi = blockIdx.x, tid = threadIdx.x;
    int wid = tid >> 5, lane = tid & 31;
    int wm = wid & 3, wn = wid >> 2;
    int l2 = lane & 15;
    int h  = bi % NH;
    int c  = (bi / NH) % NC;
    int b  = (bi / (NH*NC)) % B_;
    int s  = bi / (NH*NC*B_);
    int sb  = s*B_ + b;
    int sbo = (1 - s)*B_ + b;
    size_t l0 = (size_t)c * CHUNKSZ;

    if (tid < 128) {
        size_t off = ((size_t)sb*L_ + l0 + tid)*NH + h;
        cum_s[tid] = g_cum[off];
        dts_s[tid] = g_dt[off];
    }
    __syncthreads();
    if (tid < 128) wj_s[tid] = dts_s[tid] * __expf(cum_s[127] - cum_s[tid]);
    __syncthreads();

    for (int idx = tid; idx < 128*64; idx += 256) {
        int j = idx >> 6, n = idx & 63;
        float cv = g_xbc[((size_t)sb *L_ + l0 + j)*CONVD + 576 + n];
        float bv = g_xbc[((size_t)sbo*L_ + l0 + j)*CONVD + 512 + n];
        __nv_bfloat16 hh, ll;
        uint32_t so = swz((uint32_t)j*128 + n*2);
        split_bf16(cv, hh, ll);
        *(__nv_bfloat16*)(smraw + CK_R1 + so)         = hh;
        *(__nv_bfloat16*)(smraw + CK_R1 + 16384 + so) = ll;
        split_bf16(bv, hh, ll);
        *(__nv_bfloat16*)(smraw + CK_R1 + 32768 + so) = hh;
        *(__nv_bfloat16*)(smraw + CK_R1 + 49152 + so) = ll;
        float bw = bv * wj_s[j];
        split_bf16(bw, hh, ll);
        uint32_t st = swz((uint32_t)n*128 + (j & 63)*2);
        int pan = j >> 6;
        *(__nv_bfloat16*)(smraw + CK_BW_H(pan) + st) = hh;
        *(__nv_bfloat16*)(smraw + CK_BW_L(pan) + st) = ll;
    }
    for (int idx = tid; idx < 128*128; idx += 256) {
        int j = idx >> 7, p = idx & 127;
        float xv = g_xbc[((size_t)sbo*L_ + l0 + j)*CONVD + h*HD + p];
        __nv_bfloat16 hh, ll; split_bf16(xv, hh, ll);
        int pan = j >> 6;
        uint32_t st = swz((uint32_t)p*128 + (j & 63)*2);
        *(__nv_bfloat16*)(smraw + CK_XT_H(pan) + st) = hh;
        *(__nv_bfloat16*)(smraw + CK_XT_L(pan) + st) = ll;
    }
    __syncthreads();

    // phase A: G = C * B^T
    float accg[2][8][4];
    #pragma unroll
    for (int mt = 0; mt < 2; mt++)
        #pragma unroll
        for (int nt = 0; nt < 8; nt++)
            #pragma unroll
            for (int q = 0; q < 4; q++) accg[mt][nt][q] = 0.f;
    #pragma unroll
    for (int ks = 0; ks < 4; ks++) {
        uint32_t ah[2][4], al[2][4];
        #pragma unroll
        for (int mt = 0; mt < 2; mt++) {
            int row = wm*32 + mt*16 + (lane & 15);
            uint32_t off = swz((uint32_t)row*128 + ks*32 + ((lane >> 4) << 4));
            ldsm_x4(ah[mt], sbase + CK_R1 + off);
            ldsm_x4(al[mt], sbase + CK_R1 + 16384 + off);
        }
        #pragma unroll
        for (int nt = 0; nt < 8; nt++) {
            int row = wn*64 + nt*8 + (l2 & 7);
            uint32_t off = swz((uint32_t)row*128 + ks*32 + ((l2 >> 3) << 4));
            uint32_t bh[2], bl[2];
            ldsm_x2(bh, sbase + CK_R1 + 32768 + off);
            ldsm_x2(bl, sbase + CK_R1 + 49152 + off);
            #pragma unroll
            for (int mt = 0; mt < 2; mt++) {
                mma_bf16(accg[mt][nt], ah[mt], bh);
                mma_bf16(accg[mt][nt], ah[mt], bl);
                mma_bf16(accg[mt][nt], al[mt], bh);
            }
        }
    }
    __syncthreads();

    {
        int r0 = lane >> 2, cj = 2*(lane & 3);
        #pragma unroll
        for (int mt = 0; mt < 2; mt++) {
            #pragma unroll
            for (int nt = 0; nt < 8; nt++) {
                int j0 = wn*64 + nt*8 + cj;
                int jl = (j0 & 63);
                #pragma unroll
                for (int half = 0; half < 2; half++) {
                    int i = wm*32 + mt*16 + r0 + half*8;
                    float ci = cum_s[i];
                    float g0 = (j0   <= i) ? accg[mt][nt][half*2]   * __expf(ci - cum_s[j0])   * dts_s[j0]   : 0.f;
                    float g1 = (j0+1 <= i) ? accg[mt][nt][half*2+1] * __expf(ci - cum_s[j0+1]) * dts_s[j0+1] : 0.f;
                    __nv_bfloat16 h0, l0b, h1, l1b;
                    split_bf16(g0, h0, l0b); split_bf16(g1, h1, l1b);
                    uint32_t st = swz((uint32_t)i*128 + jl*2);
                    *(__nv_bfloat162*)(smraw + CK_GH(wn) + st) = __nv_bfloat162(h0, h1);
                    *(__nv_bfloat162*)(smraw + CK_GL(wn) + st) = __nv_bfloat162(l0b, l1b);
                }
            }
        }
    }
    __syncthreads();

    // phase B: Y = G @ X
    {
        float accy[2][8][4];
        #pragma unroll
        for (int mt = 0; mt < 2; mt++)
            #pragma unroll
            for (int nt = 0; nt < 8; nt++)
                #pragma unroll
                for (int q = 0; q < 4; q++) accy[mt][nt][q] = 0.f;
        #pragma unroll
        for (int pan = 0; pan < 2; pan++) {
            #pragma unroll
            for (int ks = 0; ks < 4; ks++) {
                uint32_t gh[2][4], gl[2][4];
                #pragma unroll
                for (int mt = 0; mt < 2; mt++) {
                    int row = wm*32 + mt*16 + (lane & 15);
                    uint32_t off = swz((uint32_t)row*128 + ks*32 + ((lane >> 4) << 4));
                    ldsm_x4(gh[mt], sbase + CK_GH(pan) + off);
                    ldsm_x4(gl[mt], sbase + CK_GL(pan) + off);
                }
                #pragma unroll
                for (int nt = 0; nt < 8; nt++) {
                    int row = wn*64 + nt*8 + (l2 & 7);
                    uint32_t off = swz((uint32_t)row*128 + ks*32 + ((l2 >> 3) << 4));
                    uint32_t xh[2], xl[2];
                    ldsm_x2(xh, sbase + CK_XT_H(pan) + off);
                    ldsm_x2(xl, sbase + CK_XT_L(pan) + off);
                    #pragma unroll
                    for (int mt = 0; mt < 2; mt++) {
                        mma_bf16(accy[mt][nt], gh[mt], xh);
                        mma_bf16(accy[mt][nt], gh[mt], xl);
                        mma_bf16(accy[mt][nt], gl[mt], xh);
                    }
                }
            }
        }
        float Dh = Dv[h];
        int r0 = lane >> 2, cp = 2*(lane & 3);
        #pragma unroll
        for (int mt = 0; mt < 2; mt++) {
            #pragma unroll
            for (int nt = 0; nt < 8; nt++) {
                int p0 = wn*64 + nt*8 + cp;
                #pragma unroll
                for (int half = 0; half < 2; half++) {
                    int i = wm*32 + mt*16 + r0 + half*8;
                    int ipan = i >> 6;
                    uint32_t b0 = swz((uint32_t)p0*128 + (i & 63)*2);
                    uint32_t b1 = swz((uint32_t)(p0+1)*128 + (i & 63)*2);
                    float x0 = __bfloat162float(*(__nv_bfloat16*)(smraw + CK_XT_H(ipan) + b0))
                             + __bfloat162float(*(__nv_bfloat16*)(smraw + CK_XT_L(ipan) + b0));
                    float x1 = __bfloat162float(*(__nv_bfloat16*)(smraw + CK_XT_H(ipan) + b1))
                             + __bfloat162float(*(__nv_bfloat16*)(smraw + CK_XT_L(ipan) + b1));
                    size_t off = ((size_t)sb*L_ + l0 + i)*DINNER + h*HD + p0;
                    *(float2*)&g_y[off] = make_float2(accy[mt][nt][half*2] + Dh*x0,
                                                      accy[mt][nt][half*2+1] + Dh*x1);
                }
            }
        }
    }

    // phase C: S = X^T @ Bw
    {
        float accs[2][4][4];
        #pragma unroll
        for (int mt = 0; mt < 2; mt++)
            #pragma unroll
            for (int nt = 0; nt < 4; nt++)
                #pragma unroll
                for (int q = 0; q < 4; q++) accs[mt][nt][q] = 0.f;
        #pragma unroll
        for (int pan = 0; pan < 2; pan++) {
            #pragma unroll
            for (int ks = 0; ks < 4; ks++) {
                uint32_t xh[2][4], xl[2][4];
                #pragma unroll
                for (int mt = 0; mt < 2; mt++) {
                    int row = wm*32 + mt*16 + (lane & 15);
                    uint32_t off = swz((uint32_t)row*128 + ks*32 + ((lane >> 4) << 4));
                    ldsm_x4(xh[mt], sbase + CK_XT_H(pan) + off);
                    ldsm_x4(xl[mt], sbase + CK_XT_L(pan) + off);
                }
                #pragma unroll
                for (int nt = 0; nt < 4; nt++) {
                    int row = wn*32 + nt*8 + (l2 & 7);
                    uint32_t off = swz((uint32_t)row*128 + ks*32 + ((l2 >> 3) << 4));
                    uint32_t bwh[2], bwl[2];
                    ldsm_x2(bwh, sbase + CK_BW_H(pan) + off);
                    ldsm_x2(bwl, sbase + CK_BW_L(pan) + off);
                    #pragma unroll
                    for (int mt = 0; mt < 2; mt++) {
                        mma_bf16(accs[mt][nt], xh[mt], bwh);
                        mma_bf16(accs[mt][nt], xh[mt], bwl);
                        mma_bf16(accs[mt][nt], xl[mt], bwh);
                    }
                }
            }
        }
        size_t sb0 = (size_t)bi * (HD*DSTATE);
        int r0 = lane >> 2, cn = 2*(lane & 3);
        #pragma unroll
        for (int mt = 0; mt < 2; mt++) {
            #pragma unroll
            for (int nt = 0; nt < 4; nt++) {
                int n0 = wn*32 + nt*8 + cn;
                #pragma unroll
                for (int half = 0; half < 2; half++) {
                    int p = wm*32 + mt*16 + r0 + half*8;
                    *(float2*)&g_state[sb0 + (size_t)p*64 + n0] =
                        make_float2(accs[mt][nt][half*2], accs[mt][nt][half*2+1]);
                }
            }
        }
    }
}

// ============================================================================
// 7. Inter-chunk scan (8 segments per (sb,h))
// ============================================================================
__global__ void scan_kernel_v2() {
    int t   = blockIdx.x >> 3;
    int seg = blockIdx.x & 7;
    int h = t % NH;
    int sb = t / NH;
    int off0 = seg * 1024 + threadIdx.x * 4;
    float4 hreg = make_float4(0.f, 0.f, 0.f, 0.f);
    for (int c = 0; c < NC; c++) {
        float dec = __expf(g_cum[((size_t)sb*L_ + c*CHUNKSZ + 127)*NH + h]);
        size_t o = (((size_t)sb*NC + c)*NH + h) * (HD*DSTATE) + off0;
        *(float4*)&g_hprev[o] = hreg;
        float4 st = *(const float4*)&g_state[o];
        hreg.x = hreg.x*dec + st.x;
        hreg.y = hreg.y*dec + st.y;
        hreg.z = hreg.z*dec + st.z;
        hreg.w = hreg.w*dec + st.w;
    }
}

// ============================================================================
// 8. Inter-chunk contribution via tensor cores
// ============================================================================
__global__ void __launch_bounds__(256)
interchunk_kernel_v2() {
    extern __shared__ char smraw[];
    uint32_t sbase = smem_to_u32(smraw);
    float* cum_s = (float*)smraw;

    int bi = blockIdx.x, tid = threadIdx.x;
    int wid = tid >> 5, lane = tid & 31;
    int wm = wid & 3, wn = wid >> 2;
    int l2 = lane & 15;
    int h  = bi % NH;
    int c  = (bi / NH) % NC;
    int b  = (bi / (NH*NC)) % B_;
    int s  = bi / (NH*NC*B_);
    int sb = s*B_ + b;
    size_t l0 = (size_t)c * CHUNKSZ;
    size_t hbase = (size_t)bi * (HD*DSTATE);

    if (tid < 128) cum_s[tid] = g_cum[((size_t)sb*L_ + l0 + tid)*NH + h];

    for (int idx = tid; idx < 128*64; idx += 256) {
        int r = idx >> 6, n = idx & 63;
        float cv = g_xbc[((size_t)sb*L_ + l0 + r)*CONVD + 576 + n];
        float hv = g_hprev[hbase + idx];
        __nv_bfloat16 hh, ll;
        uint32_t so = swz((uint32_t)r*128 + n*2);
        split_bf16(cv, hh, ll);
        *(__nv_bfloat16*)(smraw + 1024 + so)         = hh;
        *(__nv_bfloat16*)(smraw + 1024 + 16384 + so) = ll;
        split_bf16(hv, hh, ll);
        *(__nv_bfloat16*)(smraw + 1024 + 32768 + so) = hh;
        *(__nv_bfloat16*)(smraw + 1024 + 49152 + so) = ll;
    }
    __syncthreads();

    float acc[2][8][4];
    #pragma unroll
    for (int mt = 0; mt < 2; mt++)
        #pragma unroll
        for (int nt = 0; nt < 8; nt++)
            #pragma unroll
            for (int q = 0; q < 4; q++) acc[mt][nt][q] = 0.f;
    #pragma unroll
    for (int ks = 0; ks < 4; ks++) {
        uint32_t ah[2][4], al[2][4];
        #pragma unroll
        for (int mt = 0; mt < 2; mt++) {
            int row = wm*32 + mt*16 + (lane & 15);
            uint32_t off = swz((uint32_t)row*128 + ks*32 + ((lane >> 4) << 4));
            ldsm_x4(ah[mt], sbase + 1024 + off);
            ldsm_x4(al[mt], sbase + 1024 + 16384 + off);
        }
        #pragma unroll
        for (int nt = 0; nt < 8; nt++) {
            int row = wn*64 + nt*8 + (l2 & 7);
            uint32_t off = swz((uint32_t)row*128 + ks*32 + ((l2 >> 3) << 4));
            uint32_t hh[2], hl[2];
            ldsm_x2(hh, sbase + 1024 + 32768 + off);
            ldsm_x2(hl, sbase + 1024 + 49152 + off);
            #pragma unroll
            for (int mt = 0; mt < 2; mt++) {
                mma_bf16(acc[mt][nt], ah[mt], hh);
                mma_bf16(acc[mt][nt], ah[mt], hl);
                mma_bf16(acc[mt][nt], al[mt], hh);
            }
        }
    }

    int r0 = lane >> 2, cp = 2*(lane & 3);
    #pragma unroll
    for (int mt = 0; mt < 2; mt++) {
        #pragma unroll
        for (int nt = 0; nt < 8; nt++) {
            int p = wn*64 + nt*8 + cp;
            #pragma unroll
            for (int half = 0; half < 2; half++) {
                int i = wm*32 + mt*16 + r0 + half*8;
                float sc = __expf(cum_s[i]);
                size_t off = ((size_t)sb*L_ + l0 + i)*DINNER + h*HD + p;
                float2 v = *(float2*)&g_y[off];
                v.x += sc * acc[mt][nt][half*2];
                v.y += sc * acc[mt][nt][half*2+1];
                *(float2*)&g_y[off] = v;
            }
        }
    }
}

// ============================================================================
// 9. Gated RMSNorm -> writes split-bf16 A operand for out_proj directly
// ============================================================================
__global__ void rmsnorm_kernel(const float* __restrict__ norm_w) {
    int row = blockIdx.x;
    int tid = threadIdx.x;
    __shared__ float red[4];
    size_t ybase = (size_t)row * DINNER;
    size_t zbase = (size_t)row * DPROJ;
    float g[4];
    float ss = 0.f;
    #pragma unroll
    for (int t = 0; t < 4; t++) {
        int d = tid + 128*t;
        float z = g_zx[zbase + d];
        float yv = g_y[ybase + d];
        float gg = yv * (z / (1.f + __expf(-z)));
        g[t] = gg;
        ss += gg*gg;
    }
    #pragma unroll
    for (int o = 16; o > 0; o >>= 1) ss += __shfl_xor_sync(0xFFFFFFFFu, ss, o);
    if ((tid & 31) == 0) red[tid >> 5] = ss;
    __syncthreads();
    float tot = red[0] + red[1] + red[2] + red[3];
    float scale = rsqrtf(tot / (float)DINNER + 1e-5f);
    #pragma unroll
    for (int t = 0; t < 4; t++) {
        int d = tid + 128*t;
        float v = g[t] * scale * norm_w[d];
        __nv_bfloat16 h, l; split_bf16(v, h, l);
        g_ah[ybase + d] = h;
        g_al[ybase + d] = l;
    }
}

// ============================================================================
extern "C" void kernel_launch(void* const* d_in, const int* in_sizes, int n_in,
                              void* d_out, int out_size) {
    const float* left   = (const float*)d_in[0];
    const float* right  = (const float*)d_in[1];
    const float* dw     = (const float*)d_in[2];
    const float* db     = (const float*)d_in[3];
    const float* inpw   = (const float*)d_in[4];
    const float* cw     = (const float*)d_in[5];
    const float* cb     = (const float*)d_in[6];
    const float* dtb    = (const float*)d_in[7];
    const float* alog   = (const float*)d_in[8];
    const float* Dv     = (const float*)d_in[9];
    const float* nw     = (const float*)d_in[10];
    const float* outw   = (const float*)d_in[11];
    float* out          = (float*)d_out;

    float *p_zx, *p_y;
    __nv_bfloat16 *p_ah, *p_al, *p_bh, *p_bl;
    cudaGetSymbolAddress((void**)&p_zx, g_zx);
    cudaGetSymbolAddress((void**)&p_y,  g_y);
    cudaGetSymbolAddress((void**)&p_ah, g_ah);
    cudaGetSymbolAddress((void**)&p_al, g_al);
    cudaGetSymbolAddress((void**)&p_bh, g_bh);
    cudaGetSymbolAddress((void**)&p_bl, g_bl);

    const int ds_smem  = (DMODEL*48 + 16*48) * 4;
    const int mma_smem = 3 * 65536;   // 196608
    const int ic_smem  = 66560;
    cudaFuncSetAttribute(downsample_kernel,    cudaFuncAttributeMaxDynamicSharedMemorySize, ds_smem);
    cudaFuncSetAttribute(mma_gemm,             cudaFuncAttributeMaxDynamicSharedMemorySize, mma_smem);
    cudaFuncSetAttribute(chunk_kernel_v2,      cudaFuncAttributeMaxDynamicSharedMemorySize, CK_SMEM);
    cudaFuncSetAttribute(interchunk_kernel_v2, cudaFuncAttributeMaxDynamicSharedMemorySize, ic_smem);

    const int M = 2*B_*L_;   // 65536

    // 1. downsample (emits split-bf16 A for in_proj)
    downsample_kernel<<<2*B_*HO*(WO/16), 256, ds_smem>>>(left, right, dw, db);

    // 2. in_proj
    {
        size_t nb = (size_t)DPROJ_PAD * DMODEL;
        cvt_split_pad<<<(unsigned)((nb + 255)/256), 256>>>(inpw, p_bh, p_bl, DPROJ, DMODEL, DPROJ_PAD);
        dim3 grid(DPROJ_PAD/128, M/128);
        mma_gemm<<<grid, 256, mma_smem>>>(p_ah, p_al, p_bh, p_bl, p_zx, M, DPROJ, DMODEL);
    }

    // 3-5
    {
        size_t tot4 = (size_t)M*CONVD/4;
        conv_split_kernel<<<(unsigned)((tot4 + 255)/256), 256>>>(cw, cb);
    }
    {
        size_t tot = (size_t)M*NH;
        dt_kernel<<<(unsigned)((tot + 255)/256), 256>>>(dtb);
    }
    cum_kernel_v2<<<2*B_*NC*NH/8, 256>>>(alog);

    // 6-8. SSD
    chunk_kernel_v2<<<2*B_*NC*NH, 256, CK_SMEM>>>(Dv);
    scan_kernel_v2<<<2*B_*NH*8, 256>>>();
    interchunk_kernel_v2<<<2*B_*NC*NH, 256, ic_smem>>>();

    // 9. rmsnorm (emits split-bf16 A for out_proj)
    rmsnorm_kernel<<<M, 128>>>(nw);

    // 10. out_proj
    {
        size_t nb = (size_t)DMODEL * DINNER;
        cvt_split_pad<<<(unsigned)((nb + 255)/256), 256>>>(outw, p_bh, p_bl, DMODEL, DINNER, DMODEL);
        dim3 grid(DMODEL/128, M/128);
        mma_gemm<<<grid, 256, mma_smem>>>(p_ah, p_al, p_bh, p_bl, out, M, DMODEL, DINNER);
    }
}

// round 7
// speedup vs baseline: 3.1607x; 1.1030x over previous
#include <cuda_runtime.h>
#include <cuda_bf16.h>
#include <math.h>
#include <stdint.h>

// ---------------- problem constants ----------------
#define B_      4
#define L_      8192
#define DMODEL  256
#define DINNER  512
#define DSTATE  64
#define NH      4
#define HD      128
#define CHUNKSZ 128
#define NC      64
#define CONVD   640
#define DPROJ   1156
#define DPROJ_PAD 1280
#define HIMG    256
#define WIMG    512
#define HO      64
#define WO      128

// ---------------- static scratch ----------------
__device__ float g_zx   [(size_t)2*B_*L_*DPROJ];
__device__ float g_xbc  [(size_t)B_*L_*CONVD];     // stream 0 only (conv+silu)
__device__ float g_dt   [(size_t)2*B_*L_*NH];
__device__ float g_cum  [(size_t)2*B_*L_*NH];
__device__ float g_y    [(size_t)2*B_*L_*DINNER];
__device__ float g_state[(size_t)2*B_*NC*NH*HD*DSTATE];
__device__ float g_hprev[(size_t)2*B_*NC*NH*HD*DSTATE];
__device__ __nv_bfloat16 g_ah[(size_t)2*B_*L_*DINNER];
__device__ __nv_bfloat16 g_al[(size_t)2*B_*L_*DINNER];
__device__ __nv_bfloat16 g_bh[(size_t)DPROJ_PAD*DMODEL];
__device__ __nv_bfloat16 g_bl[(size_t)DPROJ_PAD*DMODEL];

// xBC row accessor: stream 0 lives in g_xbc (post conv+silu);
// stream 1 is the raw in_proj slice, read straight from g_zx.
__device__ __forceinline__ const float* xbc_row(int sbb, size_t l) {
    return (sbb < B_) ? &g_xbc[((size_t)sbb*L_ + l)*CONVD]
                      : &g_zx [((size_t)sbb*L_ + l)*DPROJ + 512];
}

// ---------------- mma.sync helpers ----------------
__device__ __forceinline__ uint32_t smem_to_u32(const void* p) {
    uint32_t a;
    asm("{ .reg .u64 t; cvta.to.shared.u64 t, %1; cvt.u32.u64 %0, t; }" : "=r"(a) : "l"(p));
    return a;
}
__device__ __forceinline__ uint32_t swz(uint32_t o) { return o ^ ((o >> 3) & 0x70); }

__device__ __forceinline__ void cp_async16(uint32_t saddr, const void* gptr) {
    asm volatile("cp.async.cg.shared.global [%0], [%1], 16;" :: "r"(saddr), "l"(gptr));
}
#define CP_COMMIT() asm volatile("cp.async.commit_group;" ::: "memory")
#define CP_WAIT(n)  asm volatile("cp.async.wait_group %0;" :: "n"(n) : "memory")

__device__ __forceinline__ void ldsm_x4(uint32_t* r, uint32_t addr) {
    asm volatile("ldmatrix.sync.aligned.m8n8.x4.shared.b16 {%0,%1,%2,%3}, [%4];"
        : "=r"(r[0]), "=r"(r[1]), "=r"(r[2]), "=r"(r[3]) : "r"(addr));
}
__device__ __forceinline__ void ldsm_x2(uint32_t* r, uint32_t addr) {
    asm volatile("ldmatrix.sync.aligned.m8n8.x2.shared.b16 {%0,%1}, [%2];"
        : "=r"(r[0]), "=r"(r[1]) : "r"(addr));
}
__device__ __forceinline__ void mma_bf16(float* c, const uint32_t* a, const uint32_t* b) {
    asm volatile("mma.sync.aligned.m16n8k16.row.col.f32.bf16.bf16.f32 "
        "{%0,%1,%2,%3}, {%4,%5,%6,%7}, {%8,%9}, {%0,%1,%2,%3};"
        : "+f"(c[0]), "+f"(c[1]), "+f"(c[2]), "+f"(c[3])
        : "r"(a[0]), "r"(a[1]), "r"(a[2]), "r"(a[3]), "r"(b[0]), "r"(b[1]));
}
__device__ __forceinline__ void split_bf16(float v, __nv_bfloat16& h, __nv_bfloat16& l) {
    h = __float2bfloat16_rn(v);
    l = __float2bfloat16_rn(v - __bfloat162float(h));
}

// ============================================================================
// split-bf16 tensor GEMM, 3-stage cp.async pipeline (round 6, passing)
// ============================================================================
__global__ void __launch_bounds__(256)
mma_gemm(const __nv_bfloat16* __restrict__ Ah, const __nv_bfloat16* __restrict__ Al,
         const __nv_bfloat16* __restrict__ Bh, const __nv_bfloat16* __restrict__ Bl,
         float* __restrict__ C, int M, int N, int K) {
    extern __shared__ char smem[];
    uint32_t sbase = smem_to_u32(smem);
    int tid = threadIdx.x, wid = tid >> 5, lane = tid & 31;
    int m0 = blockIdx.y * 128, n0 = blockIdx.x * 128;
    int wm = wid & 3, wn = wid >> 2;

    float acc[2][8][4];
    #pragma unroll
    for (int mt = 0; mt < 2; mt++)
        #pragma unroll
        for (int nt = 0; nt < 8; nt++)
            #pragma unroll
            for (int q = 0; q < 4; q++) acc[mt][nt][q] = 0.f;

    const int KT = K >> 6;
    int lrow = tid >> 3, lc8 = tid & 7;

    auto issue = [&](int kt) {
        uint32_t so = (uint32_t)(kt % 3) * 65536u;
        #pragma unroll
        for (int u = 0; u < 4; u++) {
            int row = lrow + 32 * u;
            uint32_t sw = swz((uint32_t)row * 128 + lc8 * 16);
            size_t aoff = ((size_t)(m0 + row) * K + kt * 64 + lc8 * 8);
            size_t boff = ((size_t)(n0 + row) * K + kt * 64 + lc8 * 8);
            cp_async16(sbase + so + sw,         Ah + aoff);
            cp_async16(sbase + so + 16384 + sw, Al + aoff);
            cp_async16(sbase + so + 32768 + sw, Bh + boff);
            cp_async16(sbase + so + 49152 + sw, Bl + boff);
        }
        CP_COMMIT();
    };

    issue(0);
    if (KT > 1) issue(1);

    for (int kt = 0; kt < KT; kt++) {
        if (kt + 1 < KT) CP_WAIT(1); else CP_WAIT(0);
        __syncthreads();
        if (kt + 2 < KT) issue(kt + 2);

        uint32_t so = (uint32_t)(kt % 3) * 65536u;
        #pragma unroll
        for (int ks = 0; ks < 4; ks++) {
            uint32_t ah[2][4], alr[2][4];
            #pragma unroll
            for (int mt = 0; mt < 2; mt++) {
                int row = wm * 32 + mt * 16 + (lane & 15);
                int kb  = ks * 32 + ((lane >> 4) << 4);
                uint32_t off = swz((uint32_t)row * 128 + kb);
                ldsm_x4(ah[mt],  sbase + so + off);
                ldsm_x4(alr[mt], sbase + so + 16384 + off);
            }
            int l2 = lane & 15;
            int nrow = wn * 64 + (l2 & 7);
            int kb2  = ks * 32 + ((l2 >> 3) << 4);
            #pragma unroll
            for (int nt = 0; nt < 8; nt++) {
                uint32_t bh[2], bl[2];
                uint32_t off = swz((uint32_t)(nrow + nt * 8) * 128 + kb2);
                ldsm_x2(bh, sbase + so + 32768 + off);
                ldsm_x2(bl, sbase + so + 49152 + off);
                #pragma unroll
                for (int mt = 0; mt < 2; mt++) {
                    mma_bf16(acc[mt][nt], ah[mt],  bh);
                    mma_bf16(acc[mt][nt], ah[mt],  bl);
                    mma_bf16(acc[mt][nt], alr[mt], bh);
                }
            }
        }
    }

    int r_base = m0 + wm * 32 + (lane >> 2);
    int c_base = n0 + wn * 64 + 2 * (lane & 3);
    #pragma unroll
    for (int mt = 0; mt < 2; mt++) {
        #pragma unroll
        for (int nt = 0; nt < 8; nt++) {
            int c = c_base + nt * 8;
            if (c < N) {
                int r = r_base + mt * 16;
                *(float2*)&C[(size_t)r * N + c]       = make_float2(acc[mt][nt][0], acc[mt][nt][1]);
                *(float2*)&C[(size_t)(r + 8) * N + c] = make_float2(acc[mt][nt][2], acc[mt][nt][3]);
            }
        }
    }
}

// ============================================================================
// weight conversion
// ============================================================================
__global__ void cvt_split_pad(const float* __restrict__ src,
                              __nv_bfloat16* __restrict__ hi,
                              __nv_bfloat16* __restrict__ lo,
                              int N, int K, int Npad) {
    size_t i = (size_t)blockIdx.x * 256 + threadIdx.x;
    if (i >= (size_t)Npad * K) return;
    int n = (int)(i / K);
    float v = (n < N) ? src[i] : 0.f;
    __nv_bfloat16 h, l; split_bf16(v, h, l);
    hi[i] = h; lo[i] = l;
}

// ============================================================================
// 1. Downsample conv -> split-bf16 A for in_proj
// ============================================================================
__global__ void downsample_kernel(const float* __restrict__ left,
                                  const float* __restrict__ right,
                                  const float* __restrict__ dw,
                                  const float* __restrict__ db) {
    extern __shared__ float sm[];
    float* sw = sm;
    float* sp = sm + DMODEL*48;
    int bi = blockIdx.x;
    int wt = bi % (WO/16);
    int oh = (bi / (WO/16)) % HO;
    int b  = (bi / (WO/16 * HO)) % B_;
    int s  = bi / (WO/16 * HO * B_);
    const float* img = s ? right : left;
    int tid = threadIdx.x;
    for (int i = tid; i < DMODEL*48; i += 256) sw[i] = dw[i];
    int ow0 = wt * 16;
    for (int i = tid; i < 16*48; i += 256) {
        int pos = i / 48, j = i % 48;
        int ci = j / 16, kh = (j % 16) / 4, kw = j % 4;
        sp[i] = img[((size_t)(b*3 + ci)*HIMG + (oh*4 + kh))*WIMG + (ow0 + pos)*4 + kw];
    }
    __syncthreads();
    int c = tid;
    float bias = db[c];
    for (int pos = 0; pos < 16; pos++) {
        float acc = bias;
        #pragma unroll
        for (int j = 0; j < 48; j++) acc += sp[pos*48 + j] * sw[c*48 + j];
        int l = oh*WO + ow0 + pos;
        size_t off = ((size_t)(s*B_ + b)*L_ + l)*DMODEL + c;
        __nv_bfloat16 h, lo; split_bf16(acc, h, lo);
        g_ah[off] = h;
        g_al[off] = lo;
    }
}

// ============================================================================
// 3. conv1d + silu, stream 0 only, sliding window (8 l-positions / thread)
// ============================================================================
__global__ void conv_split_kernel_v2(const float* __restrict__ cw,
                                     const float* __restrict__ cb) {
    int idx = blockIdx.x * 256 + threadIdx.x;
    const int NC4 = CONVD/4;         // 160
    int c4 = idx % NC4;
    int t  = idx / NC4;              // (sb, l-tile)
    if (t >= B_ * (L_/8)) return;
    int lt = t % (L_/8);
    int sb = t / (L_/8);
    int l0 = lt * 8;
    int ch = c4 * 4;

    // weights: 4 channels x 4 taps
    float4 w0 = *(const float4*)&cw[(ch+0)*4];
    float4 w1 = *(const float4*)&cw[(ch+1)*4];
    float4 w2 = *(const float4*)&cw[(ch+2)*4];
    float4 w3 = *(const float4*)&cw[(ch+3)*4];
    float4 bias = *(const float4*)&cb[ch];

    // window: rows l0-3 .. l0+7 (11 rows)
    float4 v[11];
    #pragma unroll
    for (int r = 0; r < 11; r++) {
        int ls = l0 - 3 + r;
        v[r] = (ls >= 0) ? *(const float4*)&g_zx[((size_t)sb*L_ + ls)*DPROJ + 512 + ch]
                         : make_float4(0.f, 0.f, 0.f, 0.f);
    }

    #pragma unroll
    for (int i = 0; i < 8; i++) {
        float a0 = bias.x + w0.x*v[i].x + w0.y*v[i+1].x + w0.z*v[i+2].x + w0.w*v[i+3].x;
        float a1 = bias.y + w1.x*v[i].y + w1.y*v[i+1].y + w1.z*v[i+2].y + w1.w*v[i+3].y;
        float a2 = bias.z + w2.x*v[i].z + w2.y*v[i+1].z + w2.z*v[i+2].z + w2.w*v[i+3].z;
        float a3 = bias.w + w3.x*v[i].w + w3.y*v[i+1].w + w3.z*v[i+2].w + w3.w*v[i+3].w;
        float4 out;
        out.x = a0 / (1.f + __expf(-a0));
        out.y = a1 / (1.f + __expf(-a1));
        out.z = a2 / (1.f + __expf(-a2));
        out.w = a3 / (1.f + __expf(-a3));
        *(float4*)&g_xbc[((size_t)sb*L_ + l0 + i)*CONVD + ch] = out;
    }
}

// ============================================================================
// 4. dt softplus
// ============================================================================
__global__ void dt_kernel(const float* __restrict__ dt_bias) {
    size_t idx = (size_t)blockIdx.x * 256 + threadIdx.x;
    if (idx >= (size_t)2*B_*L_*NH) return;
    int h = (int)(idx % NH);
    size_t row = idx / NH;
    float v = g_zx[row*DPROJ + (DINNER + CONVD) + h] + dt_bias[h];
    g_dt[idx] = (v > 20.f) ? v : log1pf(__expf(v));
}

// ============================================================================
// 5. per-chunk cumsum (warp-parallel)
// ============================================================================
__global__ void cum_kernel_v2(const float* __restrict__ A_log) {
    int gw = blockIdx.x * 8 + (threadIdx.x >> 5);
    int lane = threadIdx.x & 31;
    if (gw >= 2*B_*NC*NH) return;
    int h = gw % NH;
    int c = (gw / NH) % NC;
    int sb = gw / (NH * NC);
    float An = -__expf(A_log[h]);
    size_t base = ((size_t)sb*L_ + c*CHUNKSZ + lane*4)*NH + h;
    float v0 = g_dt[base], v1 = g_dt[base + NH], v2 = g_dt[base + 2*NH], v3 = g_dt[base + 3*NH];
    float p0 = v0, p1 = p0 + v1, p2 = p1 + v2, p3 = p2 + v3;
    float incl = p3;
    #pragma unroll
    for (int o = 1; o < 32; o <<= 1) {
        float t = __shfl_up_sync(0xFFFFFFFFu, incl, o);
        if (lane >= o) incl += t;
    }
    float ex = incl - p3;
    g_cum[base]        = An * (ex + p0);
    g_cum[base + NH]   = An * (ex + p1);
    g_cum[base + 2*NH] = An * (ex + p2);
    g_cum[base + 3*NH] = An * (ex + p3);
}

// ============================================================================
// 6. Intra-chunk SSD via tensor cores
// ============================================================================
#define CK_XT_H(p) (2048u + (uint32_t)(p)*16384u)
#define CK_XT_L(p) (34816u + (uint32_t)(p)*16384u)
#define CK_BW_H(p) (67584u + (uint32_t)(p)*8192u)
#define CK_BW_L(p) (83968u + (uint32_t)(p)*8192u)
#define CK_R1      100352u
#define CK_GH(p)   (CK_R1 + (uint32_t)(p)*16384u)
#define CK_GL(p)   (CK_R1 + 32768u + (uint32_t)(p)*16384u)
#define CK_SMEM    165888

__global__ void __launch_bounds__(256)
chunk_kernel_v2(const float* __restrict__ Dv) {
    extern __shared__ char smraw[];
    uint32_t sbase = smem_to_u32(smraw);
    float* cum_s = (float*)smraw;
    float* dts_s = (float*)(smraw + 512);
    float* wj_s  = (float*)(smraw + 1024);

    int bi = blockIdx.x, tid = threadIdx.x;
    int wid = tid >> 5, lane = tid & 31;
    int wm = wid & 3, wn = wid >> 2;
    int l2 = lane & 15;
    int h  = bi % NH;
    int c  = (bi / NH) % NC;
    int b  = (bi / (NH*NC)) % B_;
    int s  = bi / (NH*NC*B_);
    int sb  = s*B_ + b;
    int sbo = (1 - s)*B_ + b;
    size_t l0 = (size_t)c * CHUNKSZ;

    if (tid < 128) {
        size_t off = ((size_t)sb*L_ + l0 + tid)*NH + h;
        cum_s[tid] = g_cum[off];
        dts_s[tid] = g_dt[off];
    }
    __syncthreads();
    if (tid < 128) wj_s[tid] = dts_s[tid] * __expf(cum_s[127] - cum_s[tid]);
    __syncthreads();

    for (int idx = tid; idx < 128*64; idx += 256) {
        int j = idx >> 6, n = idx & 63;
        float cv = xbc_row(sb,  l0 + j)[576 + n];
        float bv = xbc_row(sbo, l0 + j)[512 + n];
        __nv_bfloat16 hh, ll;
        uint32_t so = swz((uint32_t)j*128 + n*2);
        split_bf16(cv, hh, ll);
        *(__nv_bfloat16*)(smraw + CK_R1 + so)         = hh;
        *(__nv_bfloat16*)(smraw + CK_R1 + 16384 + so) = ll;
        split_bf16(bv, hh, ll);
        *(__nv_bfloat16*)(smraw + CK_R1 + 32768 + so) = hh;
        *(__nv_bfloat16*)(smraw + CK_R1 + 49152 + so) = ll;
        float bw = bv * wj_s[j];
        split_bf16(bw, hh, ll);
        uint32_t st = swz((uint32_t)n*128 + (j & 63)*2);
        int pan = j >> 6;
        *(__nv_bfloat16*)(smraw + CK_BW_H(pan) + st) = hh;
        *(__nv_bfloat16*)(smraw + CK_BW_L(pan) + st) = ll;
    }
    for (int idx = tid; idx < 128*128; idx += 256) {
        int j = idx >> 7, p = idx & 127;
        float xv = xbc_row(sbo, l0 + j)[h*HD + p];
        __nv_bfloat16 hh, ll; split_bf16(xv, hh, ll);
        int pan = j >> 6;
        uint32_t st = swz((uint32_t)p*128 + (j & 63)*2);
        *(__nv_bfloat16*)(smraw + CK_XT_H(pan) + st) = hh;
        *(__nv_bfloat16*)(smraw + CK_XT_L(pan) + st) = ll;
    }
    __syncthreads();

    // phase A: G = C * B^T
    float accg[2][8][4];
    #pragma unroll
    for (int mt = 0; mt < 2; mt++)
        #pragma unroll
        for (int nt = 0; nt < 8; nt++)
            #pragma unroll
            for (int q = 0; q < 4; q++) accg[mt][nt][q] = 0.f;
    #pragma unroll
    for (int ks = 0; ks < 4; ks++) {
        uint32_t ah[2][4], al[2][4];
        #pragma unroll
        for (int mt = 0; mt < 2; mt++) {
            int row = wm*32 + mt*16 + (lane & 15);
            uint32_t off = swz((uint32_t)row*128 + ks*32 + ((lane >> 4) << 4));
            ldsm_x4(ah[mt], sbase + CK_R1 + off);
            ldsm_x4(al[mt], sbase + CK_R1 + 16384 + off);
        }
        #pragma unroll
        for (int nt = 0; nt < 8; nt++) {
            int row = wn*64 + nt*8 + (l2 & 7);
            uint32_t off = swz((uint32_t)row*128 + ks*32 + ((l2 >> 3) << 4));
            uint32_t bh[2], bl[2];
            ldsm_x2(bh, sbase + CK_R1 + 32768 + off);
            ldsm_x2(bl, sbase + CK_R1 + 49152 + off);
            #pragma unroll
            for (int mt = 0; mt < 2; mt++) {
                mma_bf16(accg[mt][nt], ah[mt], bh);
                mma_bf16(accg[mt][nt], ah[mt], bl);
                mma_bf16(accg[mt][nt], al[mt], bh);
            }
        }
    }
    __syncthreads();

    {
        int r0 = lane >> 2, cj = 2*(lane & 3);
        #pragma unroll
        for (int mt = 0; mt < 2; mt++) {
            #pragma unroll
            for (int nt = 0; nt < 8; nt++) {
                int j0 = wn*64 + nt*8 + cj;
                int jl = (j0 & 63);
                #pragma unroll
                for (int half = 0; half < 2; half++) {
                    int i = wm*32 + mt*16 + r0 + half*8;
                    float ci = cum_s[i];
                    float g0 = (j0   <= i) ? accg[mt][nt][half*2]   * __expf(ci - cum_s[j0])   * dts_s[j0]   : 0.f;
                    float g1 = (j0+1 <= i) ? accg[mt][nt][half*2+1] * __expf(ci - cum_s[j0+1]) * dts_s[j0+1] : 0.f;
                    __nv_bfloat16 h0, l0b, h1, l1b;
                    split_bf16(g0, h0, l0b); split_bf16(g1, h1, l1b);
                    uint32_t st = swz((uint32_t)i*128 + jl*2);
                    *(__nv_bfloat162*)(smraw + CK_GH(wn) + st) = __nv_bfloat162(h0, h1);
                    *(__nv_bfloat162*)(smraw + CK_GL(wn) + st) = __nv_bfloat162(l0b, l1b);
                }
            }
        }
    }
    __syncthreads();

    // phase B: Y = G @ X
    {
        float accy[2][8][4];
        #pragma unroll
        for (int mt = 0; mt < 2; mt++)
            #pragma unroll
            for (int nt = 0; nt < 8; nt++)
                #pragma unroll
                for (int q = 0; q < 4; q++) accy[mt][nt][q] = 0.f;
        #pragma unroll
        for (int pan = 0; pan < 2; pan++) {
            #pragma unroll
            for (int ks = 0; ks < 4; ks++) {
                uint32_t gh[2][4], gl[2][4];
                #pragma unroll
                for (int mt = 0; mt < 2; mt++) {
                    int row = wm*32 + mt*16 + (lane & 15);
                    uint32_t off = swz((uint32_t)row*128 + ks*32 + ((lane >> 4) << 4));
                    ldsm_x4(gh[mt], sbase + CK_GH(pan) + off);
                    ldsm_x4(gl[mt], sbase + CK_GL(pan) + off);
                }
                #pragma unroll
                for (int nt = 0; nt < 8; nt++) {
                    int row = wn*64 + nt*8 + (l2 & 7);
                    uint32_t off = swz((uint32_t)row*128 + ks*32 + ((l2 >> 3) << 4));
                    uint32_t xh[2], xl[2];
                    ldsm_x2(xh, sbase + CK_XT_H(pan) + off);
                    ldsm_x2(xl, sbase + CK_XT_L(pan) + off);
                    #pragma unroll
                    for (int mt = 0; mt < 2; mt++) {
                        mma_bf16(accy[mt][nt], gh[mt], xh);
                        mma_bf16(accy[mt][nt], gh[mt], xl);
                        mma_bf16(accy[mt][nt], gl[mt], xh);
                    }
                }
            }
        }
        float Dh = Dv[h];
        int r0 = lane >> 2, cp = 2*(lane & 3);
        #pragma unroll
        for (int mt = 0; mt < 2; mt++) {
            #pragma unroll
            for (int nt = 0; nt < 8; nt++) {
                int p0 = wn*64 + nt*8 + cp;
                #pragma unroll
                for (int half = 0; half < 2; half++) {
                    int i = wm*32 + mt*16 + r0 + half*8;
                    int ipan = i >> 6;
                    uint32_t b0 = swz((uint32_t)p0*128 + (i & 63)*2);
                    uint32_t b1 = swz((uint32_t)(p0+1)*128 + (i & 63)*2);
                    float x0 = __bfloat162float(*(__nv_bfloat16*)(smraw + CK_XT_H(ipan) + b0))
                             + __bfloat162float(*(__nv_bfloat16*)(smraw + CK_XT_L(ipan) + b0));
                    float x1 = __bfloat162float(*(__nv_bfloat16*)(smraw + CK_XT_H(ipan) + b1))
                             + __bfloat162float(*(__nv_bfloat16*)(smraw + CK_XT_L(ipan) + b1));
                    size_t off = ((size_t)sb*L_ + l0 + i)*DINNER + h*HD + p0;
                    *(float2*)&g_y[off] = make_float2(accy[mt][nt][half*2] + Dh*x0,
                                                      accy[mt][nt][half*2+1] + Dh*x1);
                }
            }
        }
    }

    // phase C: S = X^T @ Bw
    {
        float accs[2][4][4];
        #pragma unroll
        for (int mt = 0; mt < 2; mt++)
            #pragma unroll
            for (int nt = 0; nt < 4; nt++)
                #pragma unroll
                for (int q = 0; q < 4; q++) accs[mt][nt][q] = 0.f;
        #pragma unroll
        for (int pan = 0; pan < 2; pan++) {
            #pragma unroll
            for (int ks = 0; ks < 4; ks++) {
                uint32_t xh[2][4], xl[2][4];
                #pragma unroll
                for (int mt = 0; mt < 2; mt++) {
                    int row = wm*32 + mt*16 + (lane & 15);
                    uint32_t off = swz((uint32_t)row*128 + ks*32 + ((lane >> 4) << 4));
                    ldsm_x4(xh[mt], sbase + CK_XT_H(pan) + off);
                    ldsm_x4(xl[mt], sbase + CK_XT_L(pan) + off);
                }
                #pragma unroll
                for (int nt = 0; nt < 4; nt++) {
                    int row = wn*32 + nt*8 + (l2 & 7);
                    uint32_t off = swz((uint32_t)row*128 + ks*32 + ((l2 >> 3) << 4));
                    uint32_t bwh[2], bwl[2];
                    ldsm_x2(bwh, sbase + CK_BW_H(pan) + off);
                    ldsm_x2(bwl, sbase + CK_BW_L(pan) + off);
                    #pragma unroll
                    for (int mt = 0; mt < 2; mt++) {
                        mma_bf16(accs[mt][nt], xh[mt], bwh);
                        mma_bf16(accs[mt][nt], xh[mt], bwl);
                        mma_bf16(accs[mt][nt], xl[mt], bwh);
                    }
                }
            }
        }
        size_t sb0 = (size_t)bi * (HD*DSTATE);
        int r0 = lane >> 2, cn = 2*(lane & 3);
        #pragma unroll
        for (int mt = 0; mt < 2; mt++) {
            #pragma unroll
            for (int nt = 0; nt < 4; nt++) {
                int n0 = wn*32 + nt*8 + cn;
                #pragma unroll
                for (int half = 0; half < 2; half++) {
                    int p = wm*32 + mt*16 + r0 + half*8;
                    *(float2*)&g_state[sb0 + (size_t)p*64 + n0] =
                        make_float2(accs[mt][nt][half*2], accs[mt][nt][half*2+1]);
                }
            }
        }
    }
}

// ============================================================================
// 7. Inter-chunk scan
// ============================================================================
__global__ void scan_kernel_v2() {
    int t   = blockIdx.x >> 3;
    int seg = blockIdx.x & 7;
    int h = t % NH;
    int sb = t / NH;
    int off0 = seg * 1024 + threadIdx.x * 4;
    float4 hreg = make_float4(0.f, 0.f, 0.f, 0.f);
    for (int c = 0; c < NC; c++) {
        float dec = __expf(g_cum[((size_t)sb*L_ + c*CHUNKSZ + 127)*NH + h]);
        size_t o = (((size_t)sb*NC + c)*NH + h) * (HD*DSTATE) + off0;
        *(float4*)&g_hprev[o] = hreg;
        float4 st = *(const float4*)&g_state[o];
        hreg.x = hreg.x*dec + st.x;
        hreg.y = hreg.y*dec + st.y;
        hreg.z = hreg.z*dec + st.z;
        hreg.w = hreg.w*dec + st.w;
    }
}

// ============================================================================
// 8. Inter-chunk contribution via tensor cores
// ============================================================================
__global__ void __launch_bounds__(256)
interchunk_kernel_v2() {
    extern __shared__ char smraw[];
    uint32_t sbase = smem_to_u32(smraw);
    float* cum_s = (float*)smraw;

    int bi = blockIdx.x, tid = threadIdx.x;
    int wid = tid >> 5, lane = tid & 31;
    int wm = wid & 3, wn = wid >> 2;
    int l2 = lane & 15;
    int h  = bi % NH;
    int c  = (bi / NH) % NC;
    int b  = (bi / (NH*NC)) % B_;
    int s  = bi / (NH*NC*B_);
    int sb = s*B_ + b;
    size_t l0 = (size_t)c * CHUNKSZ;
    size_t hbase = (size_t)bi * (HD*DSTATE);

    if (tid < 128) cum_s[tid] = g_cum[((size_t)sb*L_ + l0 + tid)*NH + h];

    for (int idx = tid; idx < 128*64; idx += 256) {
        int r = idx >> 6, n = idx & 63;
        float cv = xbc_row(sb, l0 + r)[576 + n];
        float hv = g_hprev[hbase + idx];
        __nv_bfloat16 hh, ll;
        uint32_t so = swz((uint32_t)r*128 + n*2);
        split_bf16(cv, hh, ll);
        *(__nv_bfloat16*)(smraw + 1024 + so)         = hh;
        *(__nv_bfloat16*)(smraw + 1024 + 16384 + so) = ll;
        split_bf16(hv, hh, ll);
        *(__nv_bfloat16*)(smraw + 1024 + 32768 + so) = hh;
        *(__nv_bfloat16*)(smraw + 1024 + 49152 + so) = ll;
    }
    __syncthreads();

    float acc[2][8][4];
    #pragma unroll
    for (int mt = 0; mt < 2; mt++)
        #pragma unroll
        for (int nt = 0; nt < 8; nt++)
            #pragma unroll
            for (int q = 0; q < 4; q++) acc[mt][nt][q] = 0.f;
    #pragma unroll
    for (int ks = 0; ks < 4; ks++) {
        uint32_t ah[2][4], al[2][4];
        #pragma unroll
        for (int mt = 0; mt < 2; mt++) {
            int row = wm*32 + mt*16 + (lane & 15);
            uint32_t off = swz((uint32_t)row*128 + ks*32 + ((lane >> 4) << 4));
            ldsm_x4(ah[mt], sbase + 1024 + off);
            ldsm_x4(al[mt], sbase + 1024 + 16384 + off);
        }
        #pragma unroll
        for (int nt = 0; nt < 8; nt++) {
            int row = wn*64 + nt*8 + (l2 & 7);
            uint32_t off = swz((uint32_t)row*128 + ks*32 + ((l2 >> 3) << 4));
            uint32_t hh[2], hl[2];
            ldsm_x2(hh, sbase + 1024 + 32768 + off);
            ldsm_x2(hl, sbase + 1024 + 49152 + off);
            #pragma unroll
            for (int mt = 0; mt < 2; mt++) {
                mma_bf16(acc[mt][nt], ah[mt], hh);
                mma_bf16(acc[mt][nt], ah[mt], hl);
                mma_bf16(acc[mt][nt], al[mt], hh);
            }
        }
    }

    int r0 = lane >> 2, cp = 2*(lane & 3);
    #pragma unroll
    for (int mt = 0; mt < 2; mt++) {
        #pragma unroll
        for (int nt = 0; nt < 8; nt++) {
            int p = wn*64 + nt*8 + cp;
            #pragma unroll
            for (int half = 0; half < 2; half++) {
                int i = wm*32 + mt*16 + r0 + half*8;
                float sc = __expf(cum_s[i]);
                size_t off = ((size_t)sb*L_ + l0 + i)*DINNER + h*HD + p;
                float2 v = *(float2*)&g_y[off];
                v.x += sc * acc[mt][nt][half*2];
                v.y += sc * acc[mt][nt][half*2+1];
                *(float2*)&g_y[off] = v;
            }
        }
    }
}

// ============================================================================
// 9. Gated RMSNorm -> split-bf16 A for out_proj
// ============================================================================
__global__ void rmsnorm_kernel(const float* __restrict__ norm_w) {
    int row = blockIdx.x;
    int tid = threadIdx.x;
    __shared__ float red[4];
    size_t ybase = (size_t)row * DINNER;
    size_t zbase = (size_t)row * DPROJ;
    float g[4];
    float ss = 0.f;
    #pragma unroll
    for (int t = 0; t < 4; t++) {
        int d = tid + 128*t;
        float z = g_zx[zbase + d];
        float yv = g_y[ybase + d];
        float gg = yv * (z / (1.f + __expf(-z)));
        g[t] = gg;
        ss += gg*gg;
    }
    #pragma unroll
    for (int o = 16; o > 0; o >>= 1) ss += __shfl_xor_sync(0xFFFFFFFFu, ss, o);
    if ((tid & 31) == 0) red[tid >> 5] = ss;
    __syncthreads();
    float tot = red[0] + red[1] + red[2] + red[3];
    float scale = rsqrtf(tot / (float)DINNER + 1e-5f);
    #pragma unroll
    for (int t = 0; t < 4; t++) {
        int d = tid + 128*t;
        float v = g[t] * scale * norm_w[d];
        __nv_bfloat16 h, l; split_bf16(v, h, l);
        g_ah[ybase + d] = h;
        g_al[ybase + d] = l;
    }
}

// ============================================================================
extern "C" void kernel_launch(void* const* d_in, const int* in_sizes, int n_in,
                              void* d_out, int out_size) {
    const float* left   = (const float*)d_in[0];
    const float* right  = (const float*)d_in[1];
    const float* dw     = (const float*)d_in[2];
    const float* db     = (const float*)d_in[3];
    const float* inpw   = (const float*)d_in[4];
    const float* cw     = (const float*)d_in[5];
    const float* cb     = (const float*)d_in[6];
    const float* dtb    = (const float*)d_in[7];
    const float* alog   = (const float*)d_in[8];
    const float* Dv     = (const float*)d_in[9];
    const float* nw     = (const float*)d_in[10];
    const float* outw   = (const float*)d_in[11];
    float* out          = (float*)d_out;

    float *p_zx;
    __nv_bfloat16 *p_ah, *p_al, *p_bh, *p_bl;
    cudaGetSymbolAddress((void**)&p_zx, g_zx);
    cudaGetSymbolAddress((void**)&p_ah, g_ah);
    cudaGetSymbolAddress((void**)&p_al, g_al);
    cudaGetSymbolAddress((void**)&p_bh, g_bh);
    cudaGetSymbolAddress((void**)&p_bl, g_bl);

    const int ds_smem  = (DMODEL*48 + 16*48) * 4;
    const int mma_smem = 3 * 65536;
    const int ic_smem  = 66560;
    cudaFuncSetAttribute(downsample_kernel,    cudaFuncAttributeMaxDynamicSharedMemorySize, ds_smem);
    cudaFuncSetAttribute(mma_gemm,             cudaFuncAttributeMaxDynamicSharedMemorySize, mma_smem);
    cudaFuncSetAttribute(chunk_kernel_v2,      cudaFuncAttributeMaxDynamicSharedMemorySize, CK_SMEM);
    cudaFuncSetAttribute(interchunk_kernel_v2, cudaFuncAttributeMaxDynamicSharedMemorySize, ic_smem);

    const int M = 2*B_*L_;   // 65536

    // 1. downsample
    downsample_kernel<<<2*B_*HO*(WO/16), 256, ds_smem>>>(left, right, dw, db);

    // 2. in_proj
    {
        size_t nb = (size_t)DPROJ_PAD * DMODEL;
        cvt_split_pad<<<(unsigned)((nb + 255)/256), 256>>>(inpw, p_bh, p_bl, DPROJ, DMODEL, DPROJ_PAD);
        dim3 grid(DPROJ_PAD/128, M/128);
        mma_gemm<<<grid, 256, mma_smem>>>(p_ah, p_al, p_bh, p_bl, p_zx, M, DPROJ, DMODEL);
    }

    // 3. conv+silu (stream 0 only; stream 1 read raw from g_zx downstream)
    {
        int total = B_ * (L_/8) * (CONVD/4);   // 655360
        conv_split_kernel_v2<<<(total + 255)/256, 256>>>(cw, cb);
    }
    {
        size_t tot = (size_t)M*NH;
        dt_kernel<<<(unsigned)((tot + 255)/256), 256>>>(dtb);
    }
    cum_kernel_v2<<<2*B_*NC*NH/8, 256>>>(alog);

    // 6-8. SSD
    chunk_kernel_v2<<<2*B_*NC*NH, 256, CK_SMEM>>>(Dv);
    scan_kernel_v2<<<2*B_*NH*8, 256>>>();
    interchunk_kernel_v2<<<2*B_*NC*NH, 256, ic_smem>>>();

    // 9. rmsnorm
    rmsnorm_kernel<<<M, 128>>>(nw);

    // 10. out_proj
    {
        size_t nb = (size_t)DMODEL * DINNER;
        cvt_split_pad<<<(unsigned)((nb + 255)/256), 256>>>(outw, p_bh, p_bl, DMODEL, DINNER, DMODEL);
        dim3 grid(DMODEL/128, M/128);
        mma_gemm<<<grid, 256, mma_smem>>>(p_ah, p_al, p_bh, p_bl, out, M, DMODEL, DINNER);
    }
}